// round 1
// baseline (speedup 1.0000x reference)
#include <cuda_runtime.h>
#include <math.h>

#define S    2048
#define H    8
#define D    64
#define NB   2
#define EMB  512
#define BQ   64
#define BJ   64
#define PAD  65

// Scratch (allocation-free rule: __device__ globals)
__device__ float g_qh[NB*H*S*D];
__device__ float g_kh[NB*H*S*D];
__device__ float g_vh[NB*H*S*D];
__device__ float g_z [NB*S*EMB];

// ---------------------------------------------------------------------------
// Kernel 1: per-head projections  y = x @ W.T + b  (64x64 per head)
// grid.x = NB*H*(S/64), grid.y = 3 (q,k,v), block = 256
// ---------------------------------------------------------------------------
__global__ __launch_bounds__(256)
void proj_kernel(const float* __restrict__ q, const float* __restrict__ k,
                 const float* __restrict__ v,
                 const float* __restrict__ Wq, const float* __restrict__ bq,
                 const float* __restrict__ Wk, const float* __restrict__ bk,
                 const float* __restrict__ Wv, const float* __restrict__ bv)
{
    __shared__ float Ws[D][PAD];
    __shared__ float Xs[64][PAD];

    int which = blockIdx.y;
    const float* X = (which == 0) ? q  : (which == 1) ? k  : v;
    const float* W = (which == 0) ? Wq : (which == 1) ? Wk : Wv;
    const float* b = (which == 0) ? bq : (which == 1) ? bk : bv;
    float*     Out = (which == 0) ? g_qh : (which == 1) ? g_kh : g_vh;

    int bid = blockIdx.x;
    int st  = bid % (S/64);
    int h   = (bid / (S/64)) % H;
    int n   = bid / ((S/64) * H);
    int s0  = st * 64;
    int tid = threadIdx.x;

    for (int idx = tid; idx < 64*64; idx += 256)
        Ws[idx >> 6][idx & 63] = W[idx];
    for (int idx = tid; idx < 64*64; idx += 256) {
        int r = idx >> 6, e = idx & 63;
        Xs[r][e] = X[(size_t)(n*S + s0 + r)*EMB + h*D + e];
    }
    __syncthreads();

    int dl = tid & 63;
    int g  = tid >> 6;
    float acc[16];
#pragma unroll
    for (int rr = 0; rr < 16; rr++) acc[rr] = 0.f;

    for (int e = 0; e < 64; e++) {
        float w = Ws[dl][e];
#pragma unroll
        for (int rr = 0; rr < 16; rr++)
            acc[rr] += Xs[g*16 + rr][e] * w;
    }
    float bb = b[dl];
#pragma unroll
    for (int rr = 0; rr < 16; rr++) {
        int r = g*16 + rr;
        Out[((size_t)(n*H + h)*S + s0 + r)*D + dl] = acc[rr] + bb;
    }
}

// ---------------------------------------------------------------------------
// Kernel 2: fused attention.
//   scores (j>i) -> online softmax -> P@V  (normalized at end)
//   Srel[i,j] = q_i . E[S-1-(i-j)] for j<=i  -> Srel@V (no normalization)
// One block per (n, h, q-tile of 64). 256 threads.
// Row i = S-1 is fully masked -> softmax is uniform 1/S; handled exactly by
// sweeping ALL j-tiles in the softmax phase for the last q-tile with masked
// value MASKX = -1e20/sqrt(512).
// ---------------------------------------------------------------------------
__global__ __launch_bounds__(256)
void attn_kernel(const float* __restrict__ E)
{
    extern __shared__ float sm[];
    float* Qs   = sm;                 // 64*PAD
    float* Ks   = Qs + 64*PAD;        // 64*PAD
    float* Vs   = Ks + 64*PAD;        // 64*PAD
    float* Ts   = Vs + 64*PAD;        // 64*PAD (probs / rel tile)
    float* Es   = Ts + 64*PAD;        // 128*PAD
    float* rowm = Es + 128*PAD;       // 64
    float* rows = rowm + 64;          // 64
    float* corr = rows + 64;          // 64

    int bid = blockIdx.x;
    int qt  = bid % (S/BQ);
    int h   = (bid / (S/BQ)) % H;
    int n   = bid / ((S/BQ) * H);
    int q0  = qt * BQ;
    int tid = threadIdx.x;

    const float* Qp = g_qh + (size_t)(n*H + h)*S*D;
    const float* Kp = g_kh + (size_t)(n*H + h)*S*D;
    const float* Vp = g_vh + (size_t)(n*H + h)*S*D;

    for (int idx = tid; idx < 64*64; idx += 256) {
        int r = idx >> 6, e = idx & 63;
        Qs[r*PAD + e] = Qp[(size_t)(q0 + r)*D + e];
    }
    if (tid < 64) { rowm[tid] = -INFINITY; rows[tid] = 0.f; }

    int dl = tid & 63;      // output dim this thread owns
    int g  = tid >> 6;      // row group (16 rows each)
    float accp[16], accr[16];
#pragma unroll
    for (int rr = 0; rr < 16; rr++) { accp[rr] = 0.f; accr[rr] = 0.f; }

    const float inv_s = 0.044194173824159216f;   // 1/sqrt(512)
    const float MASKX = -1e20f * inv_s;
    const bool  lastq = (q0 == S - BQ);

    int ti = tid >> 2;      // score row
    int jg = tid & 3;       // score col group (16 cols each)

    for (int j0 = 0; j0 < S; j0 += BJ) {
        bool doP = (j0 >= q0) || lastq;
        bool doR = (j0 <= q0);

        __syncthreads();    // previous iteration done with Ks/Vs/Ts
        for (int idx = tid; idx < 64*64; idx += 256) {
            int r = idx >> 6, e = idx & 63;
            Vs[r*PAD + e] = Vp[(size_t)(j0 + r)*D + e];
            if (doP) Ks[r*PAD + e] = Kp[(size_t)(j0 + r)*D + e];
        }
        if (doR) {
            int l0 = S - 1 - q0 + j0 - 63;   // always >= 0
            for (int idx = tid; idx < 128*64; idx += 256) {
                int r = idx >> 6, e = idx & 63;
                int l = l0 + r;
                Es[r*PAD + e] = (l < S) ? E[(size_t)l*D + e] : 0.f;
            }
        }
        __syncthreads();

        if (doP) {
            float dot[16];
#pragma unroll
            for (int jj = 0; jj < 16; jj++) dot[jj] = 0.f;
            for (int e = 0; e < 64; e++) {
                float qv = Qs[ti*PAD + e];
#pragma unroll
                for (int jj = 0; jj < 16; jj++)
                    dot[jj] += qv * Ks[(jg*16 + jj)*PAD + e];
            }
            float x[16];
            float tmax = -INFINITY;
#pragma unroll
            for (int jj = 0; jj < 16; jj++) {
                int tj = jg*16 + jj;
                float xv = (j0 + tj > q0 + ti) ? dot[jj]*inv_s : MASKX;
                x[jj] = xv;
                tmax = fmaxf(tmax, xv);
            }
            tmax = fmaxf(tmax, __shfl_xor_sync(0xffffffffu, tmax, 1));
            tmax = fmaxf(tmax, __shfl_xor_sync(0xffffffffu, tmax, 2));
            float oldm = rowm[ti];
            float newm = fmaxf(oldm, tmax);
            float psum = 0.f;
#pragma unroll
            for (int jj = 0; jj < 16; jj++) {
                float p = expf(x[jj] - newm);
                Ts[ti*PAD + jg*16 + jj] = p;
                psum += p;
            }
            psum += __shfl_xor_sync(0xffffffffu, psum, 1);
            psum += __shfl_xor_sync(0xffffffffu, psum, 2);
            if (jg == 0) {
                float c = expf(oldm - newm);
                corr[ti] = c;
                rows[ti] = rows[ti]*c + psum;
                rowm[ti] = newm;
            }
            __syncthreads();

#pragma unroll
            for (int rr = 0; rr < 16; rr++)
                accp[rr] *= corr[g*16 + rr];
            for (int j = 0; j < 64; j++) {
                float vv = Vs[j*PAD + dl];
#pragma unroll
                for (int rr = 0; rr < 16; rr++)
                    accp[rr] += Ts[(g*16 + rr)*PAD + j] * vv;
            }
        }

        if (doR) {
            __syncthreads();   // P-phase done reading Ts before overwrite
            float dot[16];
#pragma unroll
            for (int jj = 0; jj < 16; jj++) dot[jj] = 0.f;
            int ebase = 63 - ti + jg*16;     // Es row for jj=0
            for (int e = 0; e < 64; e++) {
                float qv = Qs[ti*PAD + e];
#pragma unroll
                for (int jj = 0; jj < 16; jj++)
                    dot[jj] += qv * Es[(ebase + jj)*PAD + e];
            }
#pragma unroll
            for (int jj = 0; jj < 16; jj++) {
                int tj = jg*16 + jj;
                float val = (j0 + tj <= q0 + ti) ? dot[jj] : 0.f;
                Ts[ti*PAD + tj] = val;
            }
            __syncthreads();

            for (int j = 0; j < 64; j++) {
                float vv = Vs[j*PAD + dl];
#pragma unroll
                for (int rr = 0; rr < 16; rr++)
                    accr[rr] += Ts[(g*16 + rr)*PAD + j] * vv;
            }
        }
    }

    __syncthreads();
#pragma unroll
    for (int rr = 0; rr < 16; rr++) {
        int r = g*16 + rr;
        float outv = accp[rr] / rows[r] + accr[rr];
        g_z[((size_t)n*S + q0 + r)*EMB + h*D + dl] = outv;
    }
}

// ---------------------------------------------------------------------------
// Kernel 3: out = z @ Wo.T + bo   ([4096,512] x [512,512])
// grid (NB*S/64, EMB/64), block 256
// ---------------------------------------------------------------------------
__global__ __launch_bounds__(256)
void outproj_kernel(const float* __restrict__ Wo, const float* __restrict__ bo,
                    float* __restrict__ out)
{
    __shared__ float Zs[64][PAD];
    __shared__ float Wt[64][PAD];

    int r0  = blockIdx.x * 64;
    int d0  = blockIdx.y * 64;
    int tid = threadIdx.x;
    int dl  = tid & 63;
    int g   = tid >> 6;

    float acc[16];
#pragma unroll
    for (int rr = 0; rr < 16; rr++) acc[rr] = 0.f;

    for (int e0 = 0; e0 < EMB; e0 += 64) {
        __syncthreads();
        for (int idx = tid; idx < 64*64; idx += 256) {
            int r = idx >> 6, e = idx & 63;
            Zs[r][e] = g_z[(size_t)(r0 + r)*EMB + e0 + e];
            Wt[r][e] = Wo[(size_t)(d0 + r)*EMB + e0 + e];
        }
        __syncthreads();
        for (int e = 0; e < 64; e++) {
            float w = Wt[dl][e];
#pragma unroll
            for (int rr = 0; rr < 16; rr++)
                acc[rr] += Zs[g*16 + rr][e] * w;
        }
    }
    float bb = bo[d0 + dl];
#pragma unroll
    for (int rr = 0; rr < 16; rr++)
        out[(size_t)(r0 + g*16 + rr)*EMB + d0 + dl] = acc[rr] + bb;
}

// ---------------------------------------------------------------------------
extern "C" void kernel_launch(void* const* d_in, const int* in_sizes, int n_in,
                              void* d_out, int out_size)
{
    const float* v  = (const float*)d_in[0];
    const float* k  = (const float*)d_in[1];
    const float* q  = (const float*)d_in[2];
    const float* Wv = (const float*)d_in[3];
    const float* bv = (const float*)d_in[4];
    const float* Wk = (const float*)d_in[5];
    const float* bk = (const float*)d_in[6];
    const float* Wq = (const float*)d_in[7];
    const float* bq = (const float*)d_in[8];
    const float* E  = (const float*)d_in[9];
    const float* Wo = (const float*)d_in[10];
    const float* bo = (const float*)d_in[11];
    float* out = (float*)d_out;

    dim3 gp(NB*H*(S/64), 3);
    proj_kernel<<<gp, 256>>>(q, k, v, Wq, bq, Wk, bk, Wv, bv);

    size_t smem = (size_t)(4*64*PAD + 128*PAD + 3*64) * sizeof(float);
    cudaFuncSetAttribute(attn_kernel,
                         cudaFuncAttributeMaxDynamicSharedMemorySize,
                         (int)smem);
    attn_kernel<<<NB*H*(S/BQ), 256, smem>>>(E);

    dim3 go(NB*S/64, EMB/64);
    outproj_kernel<<<go, 256>>>(Wo, bo, out);
}

// round 2
// speedup vs baseline: 2.1363x; 2.1363x over previous
#include <cuda_runtime.h>
#include <math.h>

#define S    2048
#define H    8
#define D    64
#define NB   2
#define EMB  512
#define BQ   64
#define BJ   64
#define PAD  65
#define KP   68      // k-major row pad (mult of 4 for float4)
#define EPAD 132     // Est row pad (mult of 4)

// Scratch (allocation-free rule: __device__ globals)
__device__ float g_qh[NB*H*S*D];
__device__ float g_kh[NB*H*S*D];
__device__ float g_vh[NB*H*S*D];
__device__ float g_z [NB*S*EMB];

// ---------------------------------------------------------------------------
// Kernel 1: per-head projections  y = x @ W.T + b  (64x64 per head)
// ---------------------------------------------------------------------------
__global__ __launch_bounds__(256)
void proj_kernel(const float* __restrict__ q, const float* __restrict__ k,
                 const float* __restrict__ v,
                 const float* __restrict__ Wq, const float* __restrict__ bq,
                 const float* __restrict__ Wk, const float* __restrict__ bk,
                 const float* __restrict__ Wv, const float* __restrict__ bv)
{
    __shared__ float Ws[D][PAD];
    __shared__ float Xs[64][PAD];

    int which = blockIdx.y;
    const float* X = (which == 0) ? q  : (which == 1) ? k  : v;
    const float* W = (which == 0) ? Wq : (which == 1) ? Wk : Wv;
    const float* b = (which == 0) ? bq : (which == 1) ? bk : bv;
    float*     Out = (which == 0) ? g_qh : (which == 1) ? g_kh : g_vh;

    int bid = blockIdx.x;
    int st  = bid % (S/64);
    int h   = (bid / (S/64)) % H;
    int n   = bid / ((S/64) * H);
    int s0  = st * 64;
    int tid = threadIdx.x;

    for (int idx = tid; idx < 64*64; idx += 256)
        Ws[idx >> 6][idx & 63] = W[idx];
    for (int idx = tid; idx < 64*64; idx += 256) {
        int r = idx >> 6, e = idx & 63;
        Xs[r][e] = X[(size_t)(n*S + s0 + r)*EMB + h*D + e];
    }
    __syncthreads();

    int dl = tid & 63;
    int g  = tid >> 6;
    float acc[16];
#pragma unroll
    for (int rr = 0; rr < 16; rr++) acc[rr] = 0.f;

    for (int e = 0; e < 64; e++) {
        float w = Ws[dl][e];
#pragma unroll
        for (int rr = 0; rr < 16; rr++)
            acc[rr] += Xs[g*16 + rr][e] * w;
    }
    float bb = b[dl];
#pragma unroll
    for (int rr = 0; rr < 16; rr++) {
        int r = g*16 + rr;
        Out[((size_t)(n*H + h)*S + s0 + r)*D + dl] = acc[rr] + bb;
    }
}

// ---------------------------------------------------------------------------
// Kernel 2: fused attention, 4x4 register-blocked microkernels.
// Thread (tx,ty): tx = tid&15 -> cols c0=4*tx, ty = tid>>4 -> rows r0=4*ty.
// Softmax state m/s lives in registers (rows owned by one warp's 16 lanes;
// cross-lane reductions via shfl within the 16-lane tx group).
// ---------------------------------------------------------------------------
__global__ __launch_bounds__(256, 2)
void attn_kernel(const float* __restrict__ E)
{
    extern __shared__ float sm[];
    float* Qt  = sm;               // [64][KP]   Qt[e][r]
    float* Kt  = Qt + 64*KP;       // [64][KP]   Kt[e][j]
    float* Vs  = Kt + 64*KP;       // [64][KP]   Vs[j][d]
    float* Pt  = Vs + 64*KP;       // [64][KP]   Pt[j][r]
    float* Est = Pt + 64*KP;       // [64][EPAD] Est[e][l], l in [0,128)

    int bid = blockIdx.x;
    int qt  = bid % (S/BQ);
    int h   = (bid / (S/BQ)) % H;
    int n   = bid / ((S/BQ) * H);
    int q0  = qt * BQ;
    int tid = threadIdx.x;
    int tx  = tid & 15;
    int ty  = tid >> 4;
    int r0  = ty * 4;
    int c0  = tx * 4;

    const float* Qp = g_qh + (size_t)(n*H + h)*S*D;
    const float* Kp = g_kh + (size_t)(n*H + h)*S*D;
    const float* Vp = g_vh + (size_t)(n*H + h)*S*D;

    // stage Q transposed: Qt[e][r]
    for (int idx = tid; idx < 64*16; idx += 256) {
        int r = idx >> 4, e4 = (idx & 15) * 4;
        float4 t = *reinterpret_cast<const float4*>(Qp + (size_t)(q0 + r)*D + e4);
        Qt[(e4+0)*KP + r] = t.x;
        Qt[(e4+1)*KP + r] = t.y;
        Qt[(e4+2)*KP + r] = t.z;
        Qt[(e4+3)*KP + r] = t.w;
    }

    const float inv_s = 0.044194173824159216f;   // 1/sqrt(512)
    const float MASKX = -1e20f * inv_s;
    const bool  lastq = (q0 == S - BQ);
    const int   i0    = q0 + r0;

    float accp[4][4], accr[4][4];
    float m[4], s[4];
#pragma unroll
    for (int a = 0; a < 4; a++) {
        m[a] = -INFINITY; s[a] = 0.f;
#pragma unroll
        for (int b = 0; b < 4; b++) { accp[a][b] = 0.f; accr[a][b] = 0.f; }
    }

    for (int j0 = 0; j0 < S; j0 += BJ) {
        bool doP = (j0 >= q0) || lastq;
        bool doR = (j0 <= q0);

        __syncthreads();    // previous iteration done with Kt/Vs/Pt/Est

        // stage V (natural [j][d], float4)
        for (int idx = tid; idx < 64*16; idx += 256) {
            int r = idx >> 4, e4 = (idx & 15) * 4;
            float4 t = *reinterpret_cast<const float4*>(Vp + (size_t)(j0 + r)*D + e4);
            *reinterpret_cast<float4*>(Vs + r*KP + e4) = t;
        }
        if (doP) {
            // stage K transposed: Kt[e][j]
            for (int idx = tid; idx < 64*16; idx += 256) {
                int r = idx >> 4, e4 = (idx & 15) * 4;
                float4 t = *reinterpret_cast<const float4*>(Kp + (size_t)(j0 + r)*D + e4);
                Kt[(e4+0)*KP + r] = t.x;
                Kt[(e4+1)*KP + r] = t.y;
                Kt[(e4+2)*KP + r] = t.z;
                Kt[(e4+3)*KP + r] = t.w;
            }
        }
        if (doR) {
            // stage E transposed & shifted: Est[e][rr] = E[l0+rr][e]
            int l0 = S - 64 - (q0 - j0);   // >= 0
            for (int idx = tid; idx < 128*16; idx += 256) {
                int rr = idx >> 4, e4 = (idx & 15) * 4;
                int l = l0 + rr;
                float4 t = make_float4(0.f, 0.f, 0.f, 0.f);
                if (l < S)
                    t = *reinterpret_cast<const float4*>(E + (size_t)l*D + e4);
                Est[(e4+0)*EPAD + rr] = t.x;
                Est[(e4+1)*EPAD + rr] = t.y;
                Est[(e4+2)*EPAD + rr] = t.z;
                Est[(e4+3)*EPAD + rr] = t.w;
            }
        }
        __syncthreads();

        if (doP) {
            // ---- scores: acc = Q @ K^T (this 64x64 tile) ----
            float acc[4][4];
#pragma unroll
            for (int a = 0; a < 4; a++)
#pragma unroll
                for (int b = 0; b < 4; b++) acc[a][b] = 0.f;
#pragma unroll 8
            for (int e = 0; e < 64; e++) {
                float4 a4 = *reinterpret_cast<const float4*>(Qt + e*KP + r0);
                float4 b4 = *reinterpret_cast<const float4*>(Kt + e*KP + c0);
                float ar[4] = {a4.x, a4.y, a4.z, a4.w};
                float br[4] = {b4.x, b4.y, b4.z, b4.w};
#pragma unroll
                for (int a = 0; a < 4; a++)
#pragma unroll
                    for (int b = 0; b < 4; b++)
                        acc[a][b] += ar[a] * br[b];
            }

            // ---- online softmax (row state in registers) ----
            float tm[4];
#pragma unroll
            for (int a = 0; a < 4; a++) {
                tm[a] = -INFINITY;
#pragma unroll
                for (int b = 0; b < 4; b++) {
                    float xv = (j0 + c0 + b > i0 + a) ? acc[a][b]*inv_s : MASKX;
                    acc[a][b] = xv;
                    tm[a] = fmaxf(tm[a], xv);
                }
            }
#pragma unroll
            for (int a = 0; a < 4; a++) {
                tm[a] = fmaxf(tm[a], __shfl_xor_sync(0xffffffffu, tm[a], 1));
                tm[a] = fmaxf(tm[a], __shfl_xor_sync(0xffffffffu, tm[a], 2));
                tm[a] = fmaxf(tm[a], __shfl_xor_sync(0xffffffffu, tm[a], 4));
                tm[a] = fmaxf(tm[a], __shfl_xor_sync(0xffffffffu, tm[a], 8));
            }
            float cor[4], psum[4];
#pragma unroll
            for (int a = 0; a < 4; a++) {
                float nm = fmaxf(m[a], tm[a]);
                cor[a] = __expf(m[a] - nm);
                psum[a] = 0.f;
#pragma unroll
                for (int b = 0; b < 4; b++) {
                    float p = __expf(acc[a][b] - nm);
                    Pt[(c0 + b)*KP + r0 + a] = p;
                    psum[a] += p;
                }
                m[a] = nm;
            }
#pragma unroll
            for (int a = 0; a < 4; a++) {
                psum[a] += __shfl_xor_sync(0xffffffffu, psum[a], 1);
                psum[a] += __shfl_xor_sync(0xffffffffu, psum[a], 2);
                psum[a] += __shfl_xor_sync(0xffffffffu, psum[a], 4);
                psum[a] += __shfl_xor_sync(0xffffffffu, psum[a], 8);
                s[a] = s[a]*cor[a] + psum[a];
            }
            __syncthreads();   // Pt visible to all

            // ---- accp = accp*cor + P @ V ----
#pragma unroll
            for (int a = 0; a < 4; a++)
#pragma unroll
                for (int b = 0; b < 4; b++) accp[a][b] *= cor[a];
#pragma unroll 8
            for (int e = 0; e < 64; e++) {
                float4 a4 = *reinterpret_cast<const float4*>(Pt + e*KP + r0);
                float4 b4 = *reinterpret_cast<const float4*>(Vs + e*KP + c0);
                float ar[4] = {a4.x, a4.y, a4.z, a4.w};
                float br[4] = {b4.x, b4.y, b4.z, b4.w};
#pragma unroll
                for (int a = 0; a < 4; a++)
#pragma unroll
                    for (int b = 0; b < 4; b++)
                        accp[a][b] += ar[a] * br[b];
            }
        }

        if (doR) {
            if (doP) __syncthreads();   // P@V done reading Pt before overwrite

            // ---- rel scores: R[a][b] = Q[r0+a] . Est[.][L0+3-a+b] ----
            float acc[4][4];
#pragma unroll
            for (int a = 0; a < 4; a++)
#pragma unroll
                for (int b = 0; b < 4; b++) acc[a][b] = 0.f;
            int L0 = 60 - r0 + c0;
#pragma unroll 4
            for (int e = 0; e < 64; e++) {
                float4 a4 = *reinterpret_cast<const float4*>(Qt + e*KP + r0);
                float4 e0 = *reinterpret_cast<const float4*>(Est + e*EPAD + L0);
                float4 e1 = *reinterpret_cast<const float4*>(Est + e*EPAD + L0 + 4);
                float ar[4] = {a4.x, a4.y, a4.z, a4.w};
                float bl[8] = {e0.x, e0.y, e0.z, e0.w, e1.x, e1.y, e1.z, e1.w};
#pragma unroll
                for (int a = 0; a < 4; a++)
#pragma unroll
                    for (int b = 0; b < 4; b++)
                        acc[a][b] += ar[a] * bl[3 - a + b];
            }
#pragma unroll
            for (int a = 0; a < 4; a++)
#pragma unroll
                for (int b = 0; b < 4; b++) {
                    float val = (j0 + c0 + b <= i0 + a) ? acc[a][b] : 0.f;
                    Pt[(c0 + b)*KP + r0 + a] = val;
                }
            __syncthreads();

            // ---- accr += R @ V ----
#pragma unroll 8
            for (int e = 0; e < 64; e++) {
                float4 a4 = *reinterpret_cast<const float4*>(Pt + e*KP + r0);
                float4 b4 = *reinterpret_cast<const float4*>(Vs + e*KP + c0);
                float ar[4] = {a4.x, a4.y, a4.z, a4.w};
                float br[4] = {b4.x, b4.y, b4.z, b4.w};
#pragma unroll
                for (int a = 0; a < 4; a++)
#pragma unroll
                    for (int b = 0; b < 4; b++)
                        accr[a][b] += ar[a] * br[b];
            }
        }
    }

    // ---- epilogue ----
#pragma unroll
    for (int a = 0; a < 4; a++) {
        float inv = 1.0f / s[a];
#pragma unroll
        for (int b = 0; b < 4; b++) {
            float outv = accp[a][b] * inv + accr[a][b];
            g_z[((size_t)n*S + q0 + r0 + a)*EMB + h*D + c0 + b] = outv;
        }
    }
}

// ---------------------------------------------------------------------------
// Kernel 3: out = z @ Wo.T + bo   ([4096,512] x [512,512])
// ---------------------------------------------------------------------------
__global__ __launch_bounds__(256)
void outproj_kernel(const float* __restrict__ Wo, const float* __restrict__ bo,
                    float* __restrict__ out)
{
    __shared__ float Zs[64][PAD];
    __shared__ float Wt[64][PAD];

    int r0  = blockIdx.x * 64;
    int d0  = blockIdx.y * 64;
    int tid = threadIdx.x;
    int dl  = tid & 63;
    int g   = tid >> 6;

    float acc[16];
#pragma unroll
    for (int rr = 0; rr < 16; rr++) acc[rr] = 0.f;

    for (int e0 = 0; e0 < EMB; e0 += 64) {
        __syncthreads();
        for (int idx = tid; idx < 64*64; idx += 256) {
            int r = idx >> 6, e = idx & 63;
            Zs[r][e] = g_z[(size_t)(r0 + r)*EMB + e0 + e];
            Wt[r][e] = Wo[(size_t)(d0 + r)*EMB + e0 + e];
        }
        __syncthreads();
        for (int e = 0; e < 64; e++) {
            float w = Wt[dl][e];
#pragma unroll
            for (int rr = 0; rr < 16; rr++)
                acc[rr] += Zs[g*16 + rr][e] * w;
        }
    }
    float bb = bo[d0 + dl];
#pragma unroll
    for (int rr = 0; rr < 16; rr++)
        out[(size_t)(r0 + g*16 + rr)*EMB + d0 + dl] = acc[rr] + bb;
}

// ---------------------------------------------------------------------------
extern "C" void kernel_launch(void* const* d_in, const int* in_sizes, int n_in,
                              void* d_out, int out_size)
{
    const float* v  = (const float*)d_in[0];
    const float* k  = (const float*)d_in[1];
    const float* q  = (const float*)d_in[2];
    const float* Wv = (const float*)d_in[3];
    const float* bv = (const float*)d_in[4];
    const float* Wk = (const float*)d_in[5];
    const float* bk = (const float*)d_in[6];
    const float* Wq = (const float*)d_in[7];
    const float* bq = (const float*)d_in[8];
    const float* E  = (const float*)d_in[9];
    const float* Wo = (const float*)d_in[10];
    const float* bo = (const float*)d_in[11];
    float* out = (float*)d_out;

    dim3 gp(NB*H*(S/64), 3);
    proj_kernel<<<gp, 256>>>(q, k, v, Wq, bq, Wk, bk, Wv, bv);

    size_t smem = (size_t)(4*64*KP + 64*EPAD) * sizeof(float);
    static bool attr_set = false;
    cudaFuncSetAttribute(attn_kernel,
                         cudaFuncAttributeMaxDynamicSharedMemorySize,
                         (int)smem);
    (void)attr_set;
    attn_kernel<<<NB*H*(S/BQ), 256, smem>>>(E);

    dim3 go(NB*S/64, EMB/64);
    outproj_kernel<<<go, 256>>>(Wo, bo, out);
}

// round 3
// speedup vs baseline: 4.3931x; 2.0564x over previous
#include <cuda_runtime.h>
#include <math.h>
#include <stdint.h>

#define S    2048
#define H    8
#define D    64
#define NB   2
#define EMB  512
#define BQ   64
#define BJ   64
#define PAD  65
#define KP   68      // Ksm pad (row-major [j][e])
#define VP   72      // Vs  pad (row-major [j][d])
#define PP   68      // Ps  pad (row-major [r][j])
#define EP   68      // Esm pad (row-major [l][e])

// Scratch (allocation-free rule: __device__ globals)
__device__ float g_qh[NB*H*S*D];
__device__ float g_kh[NB*H*S*D];
__device__ float g_vh[NB*H*S*D];
__device__ float g_z [NB*S*EMB];

// ---------------------------------------------------------------------------
// tf32 helpers
// ---------------------------------------------------------------------------
__device__ __forceinline__ uint32_t f2tf(float f) {
    uint32_t r;
    asm("cvt.rna.tf32.f32 %0, %1;" : "=r"(r) : "f"(f));
    return r;
}
__device__ __forceinline__ float f2tff(float f) { return __uint_as_float(f2tf(f)); }

__device__ __forceinline__ void mma8(float c[4],
                                     uint32_t a0, uint32_t a1, uint32_t a2, uint32_t a3,
                                     uint32_t b0, uint32_t b1)
{
    asm volatile(
        "mma.sync.aligned.m16n8k8.row.col.f32.tf32.tf32.f32 "
        "{%0,%1,%2,%3}, {%4,%5,%6,%7}, {%8,%9}, {%0,%1,%2,%3};"
        : "+f"(c[0]), "+f"(c[1]), "+f"(c[2]), "+f"(c[3])
        : "r"(a0), "r"(a1), "r"(a2), "r"(a3), "r"(b0), "r"(b1));
}

// ---------------------------------------------------------------------------
// Kernel 1: per-head projections  y = x @ W.T + b  (64x64 per head)
// ---------------------------------------------------------------------------
__global__ __launch_bounds__(256)
void proj_kernel(const float* __restrict__ q, const float* __restrict__ k,
                 const float* __restrict__ v,
                 const float* __restrict__ Wq, const float* __restrict__ bq,
                 const float* __restrict__ Wk, const float* __restrict__ bk,
                 const float* __restrict__ Wv, const float* __restrict__ bv)
{
    __shared__ float Ws[D][PAD];
    __shared__ float Xs[64][PAD];

    int which = blockIdx.y;
    const float* X = (which == 0) ? q  : (which == 1) ? k  : v;
    const float* W = (which == 0) ? Wq : (which == 1) ? Wk : Wv;
    const float* b = (which == 0) ? bq : (which == 1) ? bk : bv;
    float*     Out = (which == 0) ? g_qh : (which == 1) ? g_kh : g_vh;

    int bid = blockIdx.x;
    int st  = bid % (S/64);
    int h   = (bid / (S/64)) % H;
    int n   = bid / ((S/64) * H);
    int s0  = st * 64;
    int tid = threadIdx.x;

    for (int idx = tid; idx < 64*64; idx += 256)
        Ws[idx >> 6][idx & 63] = W[idx];
    for (int idx = tid; idx < 64*64; idx += 256) {
        int r = idx >> 6, e = idx & 63;
        Xs[r][e] = X[(size_t)(n*S + s0 + r)*EMB + h*D + e];
    }
    __syncthreads();

    int dl = tid & 63;
    int g  = tid >> 6;
    float acc[16];
#pragma unroll
    for (int rr = 0; rr < 16; rr++) acc[rr] = 0.f;

    for (int e = 0; e < 64; e++) {
        float w = Ws[dl][e];
#pragma unroll
        for (int rr = 0; rr < 16; rr++)
            acc[rr] += Xs[g*16 + rr][e] * w;
    }
    float bb = b[dl];
#pragma unroll
    for (int rr = 0; rr < 16; rr++) {
        int r = g*16 + rr;
        Out[((size_t)(n*H + h)*S + s0 + r)*D + dl] = acc[rr] + bb;
    }
}

// ---------------------------------------------------------------------------
// Kernel 2: fused attention on tensor cores (mma.sync m16n8k8 tf32).
// 128 threads = 4 warps; warp wr owns rows [wr*16, wr*16+16) of the 64-row
// q-tile and ALL 64 output columns. Softmax state lives in registers,
// reductions are quad-shuffles. Q is pre-loaded once as tf32 A-fragments.
// Srel: QE[64x128] GEMM per j-tile, diagonal-scattered into Ps, then R@V mma.
// ---------------------------------------------------------------------------
__global__ __launch_bounds__(128, 2)
void attn_kernel(const float* __restrict__ E)
{
    extern __shared__ float sm[];
    float* Ksm = sm;                 // [64][KP]   K[j][e]  (tf32)
    float* Vs  = Ksm + 64*KP;        // [64][VP]   V[j][d]  (tf32)
    float* Ps  = Vs  + 64*VP;        // [64][PP]   P/R[r][j] (tf32)
    float* Esm = Ps  + 64*PP;        // [128][EP]  E[l][e]  (tf32)

    int bid = blockIdx.x;
    int qt  = (S/BQ - 1) - (bid % (S/BQ));   // heavy tiles first
    int h   = (bid / (S/BQ)) % H;
    int n   = bid / ((S/BQ) * H);
    int q0  = qt * BQ;
    int tid  = threadIdx.x;
    int lane = tid & 31;
    int wr   = tid >> 5;
    int lq   = lane >> 2;     // 0..7
    int lr   = lane & 3;      // 0..3

    const float* Qp = g_qh + (size_t)(n*H + h)*S*D;
    const float* Kp = g_kh + (size_t)(n*H + h)*S*D;
    const float* Vp = g_vh + (size_t)(n*H + h)*S*D;

    // ---- Q fragments (tf32), resident for the whole block ----
    uint32_t qa[8][4];
    {
        const float* qlo = Qp + (size_t)(q0 + wr*16 + lq)*D;
        const float* qhi = qlo + 8*D;
#pragma unroll
        for (int ks = 0; ks < 8; ks++) {
            qa[ks][0] = f2tf(qlo[ks*8 + lr]);
            qa[ks][1] = f2tf(qhi[ks*8 + lr]);
            qa[ks][2] = f2tf(qlo[ks*8 + 4 + lr]);
            qa[ks][3] = f2tf(qhi[ks*8 + 4 + lr]);
        }
    }

    float accp[8][4], accr[8][4];
#pragma unroll
    for (int nt = 0; nt < 8; nt++)
#pragma unroll
        for (int i = 0; i < 4; i++) { accp[nt][i] = 0.f; accr[nt][i] = 0.f; }

    float m0 = -INFINITY, m1 = -INFINITY, s0 = 0.f, s1 = 0.f;

    const float inv_s = 0.044194173824159216f;   // 1/sqrt(512)
    const float MASKX = -1e20f * inv_s;
    const bool  lastq = (qt == S/BQ - 1);
    const int   ilo   = q0 + wr*16 + lq;          // global row of c0/c1
    const int   rlo   = wr*16 + lq;               // local row

    for (int j0 = 0; j0 < S; j0 += BJ) {
        bool doP = (j0 >= q0) || lastq;
        bool doR = (j0 <= q0);

        __syncthreads();    // all warps done with Ksm/Vs/Esm of prev tile

        // ---- stage V (always), K (doP), E window (doR); convert to tf32 ----
        for (int t = tid; t < 64*16; t += 128) {
            int r = t >> 4, e4 = (t & 15) * 4;
            float4 x = *reinterpret_cast<const float4*>(Vp + (size_t)(j0 + r)*D + e4);
            float4 y = make_float4(f2tff(x.x), f2tff(x.y), f2tff(x.z), f2tff(x.w));
            *reinterpret_cast<float4*>(Vs + r*VP + e4) = y;
        }
        if (doP) {
            for (int t = tid; t < 64*16; t += 128) {
                int r = t >> 4, e4 = (t & 15) * 4;
                float4 x = *reinterpret_cast<const float4*>(Kp + (size_t)(j0 + r)*D + e4);
                float4 y = make_float4(f2tff(x.x), f2tff(x.y), f2tff(x.z), f2tff(x.w));
                *reinterpret_cast<float4*>(Ksm + r*KP + e4) = y;
            }
        }
        if (doR) {
            int l0 = S - 64 - (q0 - j0);   // >= 0
            for (int t = tid; t < 128*16; t += 128) {
                int rr = t >> 4, e4 = (t & 15) * 4;
                int l = l0 + rr;
                float4 y = make_float4(0.f, 0.f, 0.f, 0.f);
                if (l < S) {
                    float4 x = *reinterpret_cast<const float4*>(E + (size_t)l*D + e4);
                    y = make_float4(f2tff(x.x), f2tff(x.y), f2tff(x.z), f2tff(x.w));
                }
                *reinterpret_cast<float4*>(Esm + rr*EP + e4) = y;
            }
        }
        __syncthreads();

        if (doP) {
            // ---- scores: sc[64x64 tile], warp = 16 rows x 64 cols ----
            float sc[8][4];
#pragma unroll
            for (int nt = 0; nt < 8; nt++)
#pragma unroll
                for (int i = 0; i < 4; i++) sc[nt][i] = 0.f;
#pragma unroll
            for (int ks = 0; ks < 8; ks++) {
#pragma unroll
                for (int nt = 0; nt < 8; nt++) {
                    uint32_t b0 = __float_as_uint(Ksm[(nt*8 + lq)*KP + ks*8 + lr]);
                    uint32_t b1 = __float_as_uint(Ksm[(nt*8 + lq)*KP + ks*8 + 4 + lr]);
                    mma8(sc[nt], qa[ks][0], qa[ks][1], qa[ks][2], qa[ks][3], b0, b1);
                }
            }

            // ---- mask + online softmax (register state, quad shfl) ----
            float tm0 = -INFINITY, tm1 = -INFINITY;
#pragma unroll
            for (int nt = 0; nt < 8; nt++) {
                int jc = j0 + nt*8 + 2*lr;
                float x0 = (jc     > ilo    ) ? sc[nt][0]*inv_s : MASKX;
                float x1 = (jc + 1 > ilo    ) ? sc[nt][1]*inv_s : MASKX;
                float x2 = (jc     > ilo + 8) ? sc[nt][2]*inv_s : MASKX;
                float x3 = (jc + 1 > ilo + 8) ? sc[nt][3]*inv_s : MASKX;
                sc[nt][0] = x0; sc[nt][1] = x1; sc[nt][2] = x2; sc[nt][3] = x3;
                tm0 = fmaxf(tm0, fmaxf(x0, x1));
                tm1 = fmaxf(tm1, fmaxf(x2, x3));
            }
            tm0 = fmaxf(tm0, __shfl_xor_sync(0xffffffffu, tm0, 1));
            tm0 = fmaxf(tm0, __shfl_xor_sync(0xffffffffu, tm0, 2));
            tm1 = fmaxf(tm1, __shfl_xor_sync(0xffffffffu, tm1, 1));
            tm1 = fmaxf(tm1, __shfl_xor_sync(0xffffffffu, tm1, 2));

            float nm0 = fmaxf(m0, tm0), nm1 = fmaxf(m1, tm1);
            float cor0 = __expf(m0 - nm0), cor1 = __expf(m1 - nm1);
            m0 = nm0; m1 = nm1;

            float ps0 = 0.f, ps1 = 0.f;
#pragma unroll
            for (int nt = 0; nt < 8; nt++) {
                float p0 = __expf(sc[nt][0] - nm0);
                float p1 = __expf(sc[nt][1] - nm0);
                float p2 = __expf(sc[nt][2] - nm1);
                float p3 = __expf(sc[nt][3] - nm1);
                ps0 += p0 + p1;  ps1 += p2 + p3;
                int cc = nt*8 + 2*lr;
                *reinterpret_cast<float2*>(Ps + rlo*PP + cc) =
                    make_float2(f2tff(p0), f2tff(p1));
                *reinterpret_cast<float2*>(Ps + (rlo + 8)*PP + cc) =
                    make_float2(f2tff(p2), f2tff(p3));
            }
            ps0 += __shfl_xor_sync(0xffffffffu, ps0, 1);
            ps0 += __shfl_xor_sync(0xffffffffu, ps0, 2);
            ps1 += __shfl_xor_sync(0xffffffffu, ps1, 1);
            ps1 += __shfl_xor_sync(0xffffffffu, ps1, 2);
            s0 = s0*cor0 + ps0;
            s1 = s1*cor1 + ps1;
            __syncwarp();

            // ---- accp = accp*cor + P @ V ----
#pragma unroll
            for (int nt = 0; nt < 8; nt++) {
                accp[nt][0] *= cor0; accp[nt][1] *= cor0;
                accp[nt][2] *= cor1; accp[nt][3] *= cor1;
            }
#pragma unroll
            for (int ks = 0; ks < 8; ks++) {
                uint32_t a0 = __float_as_uint(Ps[ rlo      *PP + ks*8     + lr]);
                uint32_t a1 = __float_as_uint(Ps[(rlo + 8) *PP + ks*8     + lr]);
                uint32_t a2 = __float_as_uint(Ps[ rlo      *PP + ks*8 + 4 + lr]);
                uint32_t a3 = __float_as_uint(Ps[(rlo + 8) *PP + ks*8 + 4 + lr]);
#pragma unroll
                for (int nt = 0; nt < 8; nt++) {
                    uint32_t b0 = __float_as_uint(Vs[(ks*8     + lr)*VP + nt*8 + lq]);
                    uint32_t b1 = __float_as_uint(Vs[(ks*8 + 4 + lr)*VP + nt*8 + lq]);
                    mma8(accp[nt], a0, a1, a2, a3, b0, b1);
                }
            }
        }

        if (doR) {
            if (doP) __syncwarp();   // P@V done reading Ps (warp-local rows)
            int dq = q0 - j0;

            // ---- QE = Q @ Ewindow^T, in two 64-col halves; scatter diag ----
#pragma unroll
            for (int half = 0; half < 2; half++) {
                float qe[8][4];
#pragma unroll
                for (int nt = 0; nt < 8; nt++)
#pragma unroll
                    for (int i = 0; i < 4; i++) qe[nt][i] = 0.f;
#pragma unroll
                for (int ks = 0; ks < 8; ks++) {
#pragma unroll
                    for (int nt = 0; nt < 8; nt++) {
                        int ln = half*64 + nt*8 + lq;
                        uint32_t b0 = __float_as_uint(Esm[ln*EP + ks*8 + lr]);
                        uint32_t b1 = __float_as_uint(Esm[ln*EP + ks*8 + 4 + lr]);
                        mma8(qe[nt], qa[ks][0], qa[ks][1], qa[ks][2], qa[ks][3], b0, b1);
                    }
                }
                // scatter: R[ri][cj] = QE[ri][rr], cj = rr - 63 + ri, mask j<=i
#pragma unroll
                for (int nt = 0; nt < 8; nt++) {
                    int rr = half*64 + nt*8 + 2*lr;
                    int cjA = rr - 63 + rlo;        // for c0 (and c1 at +1)
                    int cjB = cjA + 8;              // row rlo+8
                    if (cjA >= 0 && cjA < 64)
                        Ps[rlo*PP + cjA] = f2tff((cjA <= dq + rlo) ? qe[nt][0] : 0.f);
                    if (cjA + 1 >= 0 && cjA + 1 < 64)
                        Ps[rlo*PP + cjA + 1] = f2tff((cjA + 1 <= dq + rlo) ? qe[nt][1] : 0.f);
                    if (cjB >= 0 && cjB < 64)
                        Ps[(rlo + 8)*PP + cjB] = f2tff((cjB <= dq + rlo + 8) ? qe[nt][2] : 0.f);
                    if (cjB + 1 >= 0 && cjB + 1 < 64)
                        Ps[(rlo + 8)*PP + cjB + 1] = f2tff((cjB + 1 <= dq + rlo + 8) ? qe[nt][3] : 0.f);
                }
            }
            __syncwarp();

            // ---- accr += R @ V ----
#pragma unroll
            for (int ks = 0; ks < 8; ks++) {
                uint32_t a0 = __float_as_uint(Ps[ rlo      *PP + ks*8     + lr]);
                uint32_t a1 = __float_as_uint(Ps[(rlo + 8) *PP + ks*8     + lr]);
                uint32_t a2 = __float_as_uint(Ps[ rlo      *PP + ks*8 + 4 + lr]);
                uint32_t a3 = __float_as_uint(Ps[(rlo + 8) *PP + ks*8 + 4 + lr]);
#pragma unroll
                for (int nt = 0; nt < 8; nt++) {
                    uint32_t b0 = __float_as_uint(Vs[(ks*8     + lr)*VP + nt*8 + lq]);
                    uint32_t b1 = __float_as_uint(Vs[(ks*8 + 4 + lr)*VP + nt*8 + lq]);
                    mma8(accr[nt], a0, a1, a2, a3, b0, b1);
                }
            }
        }
    }

    // ---- epilogue ----
    float i0v = 1.0f / s0, i1v = 1.0f / s1;
#pragma unroll
    for (int nt = 0; nt < 8; nt++) {
        int col = h*D + nt*8 + 2*lr;
        float2 lo = make_float2(accp[nt][0]*i0v + accr[nt][0],
                                accp[nt][1]*i0v + accr[nt][1]);
        float2 hi = make_float2(accp[nt][2]*i1v + accr[nt][2],
                                accp[nt][3]*i1v + accr[nt][3]);
        *reinterpret_cast<float2*>(g_z + ((size_t)n*S + ilo    )*EMB + col) = lo;
        *reinterpret_cast<float2*>(g_z + ((size_t)n*S + ilo + 8)*EMB + col) = hi;
    }
}

// ---------------------------------------------------------------------------
// Kernel 3: out = z @ Wo.T + bo   ([4096,512] x [512,512])
// ---------------------------------------------------------------------------
__global__ __launch_bounds__(256)
void outproj_kernel(const float* __restrict__ Wo, const float* __restrict__ bo,
                    float* __restrict__ out)
{
    __shared__ float Zs[64][PAD];
    __shared__ float Wt[64][PAD];

    int r0  = blockIdx.x * 64;
    int d0  = blockIdx.y * 64;
    int tid = threadIdx.x;
    int dl  = tid & 63;
    int g   = tid >> 6;

    float acc[16];
#pragma unroll
    for (int rr = 0; rr < 16; rr++) acc[rr] = 0.f;

    for (int e0 = 0; e0 < EMB; e0 += 64) {
        __syncthreads();
        for (int idx = tid; idx < 64*64; idx += 256) {
            int r = idx >> 6, e = idx & 63;
            Zs[r][e] = g_z[(size_t)(r0 + r)*EMB + e0 + e];
            Wt[r][e] = Wo[(size_t)(d0 + r)*EMB + e0 + e];
        }
        __syncthreads();
        for (int e = 0; e < 64; e++) {
            float w = Wt[dl][e];
#pragma unroll
            for (int rr = 0; rr < 16; rr++)
                acc[rr] += Zs[g*16 + rr][e] * w;
        }
    }
    float bb = bo[d0 + dl];
#pragma unroll
    for (int rr = 0; rr < 16; rr++)
        out[(size_t)(r0 + g*16 + rr)*EMB + d0 + dl] = acc[rr] + bb;
}

// ---------------------------------------------------------------------------
extern "C" void kernel_launch(void* const* d_in, const int* in_sizes, int n_in,
                              void* d_out, int out_size)
{
    const float* v  = (const float*)d_in[0];
    const float* k  = (const float*)d_in[1];
    const float* q  = (const float*)d_in[2];
    const float* Wv = (const float*)d_in[3];
    const float* bv = (const float*)d_in[4];
    const float* Wk = (const float*)d_in[5];
    const float* bk = (const float*)d_in[6];
    const float* Wq = (const float*)d_in[7];
    const float* bq = (const float*)d_in[8];
    const float* E  = (const float*)d_in[9];
    const float* Wo = (const float*)d_in[10];
    const float* bo = (const float*)d_in[11];
    float* out = (float*)d_out;

    dim3 gp(NB*H*(S/64), 3);
    proj_kernel<<<gp, 256>>>(q, k, v, Wq, bq, Wk, bk, Wv, bv);

    size_t smem = (size_t)(64*KP + 64*VP + 64*PP + 128*EP) * sizeof(float);
    cudaFuncSetAttribute(attn_kernel,
                         cudaFuncAttributeMaxDynamicSharedMemorySize,
                         (int)smem);
    attn_kernel<<<NB*H*(S/BQ), 128, smem>>>(E);

    dim3 go(NB*S/64, EMB/64);
    outproj_kernel<<<go, 256>>>(Wo, bo, out);
}

// round 4
// speedup vs baseline: 5.9965x; 1.3650x over previous
#include <cuda_runtime.h>
#include <cuda_fp16.h>
#include <math.h>
#include <stdint.h>

#define S    2048
#define H    8
#define D    64
#define NB   2
#define EMB  512
#define BQ   64
#define BJ   64
#define KP2  72      // Ksm pad (halves)
#define VP2  66      // Vt  pad (halves)
#define PP2  72      // Psh pad (halves)
#define EP2  72      // Esm pad (halves)
#define GP   68      // generic float pad for GEMM kernels

// Scratch (allocation-free rule: __device__ globals)
__device__ float g_qh[NB*H*S*D];
__device__ float g_kh[NB*H*S*D];
__device__ float g_vh[NB*H*S*D];
__device__ float g_z [NB*S*EMB];

// ---------------------------------------------------------------------------
// helpers
// ---------------------------------------------------------------------------
__device__ __forceinline__ uint32_t h2u(float a, float b) {
    __half2 h = __floats2half2_rn(a, b);
    return *reinterpret_cast<uint32_t*>(&h);
}

__device__ __forceinline__ void mma16(float c[4],
                                      uint32_t a0, uint32_t a1, uint32_t a2, uint32_t a3,
                                      uint32_t b0, uint32_t b1)
{
    asm volatile(
        "mma.sync.aligned.m16n8k16.row.col.f32.f16.f16.f32 "
        "{%0,%1,%2,%3}, {%4,%5,%6,%7}, {%8,%9}, {%0,%1,%2,%3};"
        : "+f"(c[0]), "+f"(c[1]), "+f"(c[2]), "+f"(c[3])
        : "r"(a0), "r"(a1), "r"(a2), "r"(a3), "r"(b0), "r"(b1));
}

// ---------------------------------------------------------------------------
// Kernel 1: per-head projections  y = x @ W.T + b  (64x64 per head)
// 4x4 float4 register-blocked microkernel, transposed smem staging.
// ---------------------------------------------------------------------------
__global__ __launch_bounds__(256)
void proj_kernel(const float* __restrict__ q, const float* __restrict__ k,
                 const float* __restrict__ v,
                 const float* __restrict__ Wq, const float* __restrict__ bq,
                 const float* __restrict__ Wk, const float* __restrict__ bk,
                 const float* __restrict__ Wv, const float* __restrict__ bv)
{
    __shared__ float Xt[64][GP];   // Xt[e][s]
    __shared__ float Wt[64][GP];   // Wt[e][d]

    int which = blockIdx.y;
    const float* X = (which == 0) ? q  : (which == 1) ? k  : v;
    const float* W = (which == 0) ? Wq : (which == 1) ? Wk : Wv;
    const float* b = (which == 0) ? bq : (which == 1) ? bk : bv;
    float*     Out = (which == 0) ? g_qh : (which == 1) ? g_kh : g_vh;

    int bid = blockIdx.x;
    int st  = bid % (S/64);
    int h   = (bid / (S/64)) % H;
    int n   = bid / ((S/64) * H);
    int s0  = st * 64;
    int tid = threadIdx.x;

    for (int idx = tid; idx < 64*16; idx += 256) {
        int r = idx >> 4, e4 = (idx & 15) * 4;
        float4 x = *reinterpret_cast<const float4*>(X + (size_t)(n*S + s0 + r)*EMB + h*D + e4);
        Xt[e4+0][r] = x.x; Xt[e4+1][r] = x.y; Xt[e4+2][r] = x.z; Xt[e4+3][r] = x.w;
        float4 w = *reinterpret_cast<const float4*>(W + (size_t)r*D + e4);
        Wt[e4+0][r] = w.x; Wt[e4+1][r] = w.y; Wt[e4+2][r] = w.z; Wt[e4+3][r] = w.w;
    }
    __syncthreads();

    int tx = tid & 15;     // d group
    int ty = tid >> 4;     // s group
    float acc[4][4];
#pragma unroll
    for (int a = 0; a < 4; a++)
#pragma unroll
        for (int c = 0; c < 4; c++) acc[a][c] = 0.f;

#pragma unroll 8
    for (int e = 0; e < 64; e++) {
        float4 xs = *reinterpret_cast<const float4*>(&Xt[e][4*ty]);
        float4 wd = *reinterpret_cast<const float4*>(&Wt[e][4*tx]);
        float xr[4] = {xs.x, xs.y, xs.z, xs.w};
        float wr[4] = {wd.x, wd.y, wd.z, wd.w};
#pragma unroll
        for (int a = 0; a < 4; a++)
#pragma unroll
            for (int c = 0; c < 4; c++)
                acc[a][c] += xr[a] * wr[c];
    }

    float4 bb = *reinterpret_cast<const float4*>(b + 4*tx);
#pragma unroll
    for (int a = 0; a < 4; a++) {
        float4 o = make_float4(acc[a][0] + bb.x, acc[a][1] + bb.y,
                               acc[a][2] + bb.z, acc[a][3] + bb.w);
        *reinterpret_cast<float4*>(Out + ((size_t)(n*H + h)*S + s0 + 4*ty + a)*D + 4*tx) = o;
    }
}

// ---------------------------------------------------------------------------
// Kernel 2: fused attention on fp16 mma.sync m16n8k16, fp32 accum.
// 128 threads = 4 warps; warp owns 16 rows. P stays in registers (C-fragment
// of score phase == A-fragment of PV phase). Srel via QE GEMM + diagonal
// scatter through smem (warp-private rows).
// ---------------------------------------------------------------------------
__global__ __launch_bounds__(128, 3)
void attn_kernel(const float* __restrict__ E)
{
    extern __shared__ __half smh[];
    __half* Ksm = smh;                 // [64][KP2]   K[j][e]
    __half* Vt  = Ksm + 64*KP2;        // [64][VP2]   V^T[d][j]
    __half* Psh = Vt  + 64*VP2;        // [64][PP2]   R[r][j]
    __half* Esm = Psh + 64*PP2;        // [128][EP2]  E[l][e]

    int bid = blockIdx.x;
    int qt  = (S/BQ - 1) - (bid % (S/BQ));   // heavy tiles first
    int h   = (bid / (S/BQ)) % H;
    int n   = bid / ((S/BQ) * H);
    int q0  = qt * BQ;
    int tid  = threadIdx.x;
    int lane = tid & 31;
    int wr   = tid >> 5;
    int lq   = lane >> 2;     // 0..7
    int lr   = lane & 3;      // 0..3

    const float* Qp = g_qh + (size_t)(n*H + h)*S*D;
    const float* Kp = g_kh + (size_t)(n*H + h)*S*D;
    const float* Vp = g_vh + (size_t)(n*H + h)*S*D;

    const int rlo = wr*16 + lq;      // local row (also +8)
    const int ilo = q0 + rlo;        // global row

    // ---- Q fragments (fp16), resident for the whole block ----
    uint32_t qa[4][4];
    {
        const float* qr0 = Qp + (size_t)ilo*D;
        const float* qr1 = qr0 + 8*D;
#pragma unroll
        for (int ks = 0; ks < 4; ks++) {
            float2 x0 = *reinterpret_cast<const float2*>(qr0 + ks*16 + 2*lr);
            float2 x1 = *reinterpret_cast<const float2*>(qr1 + ks*16 + 2*lr);
            float2 x2 = *reinterpret_cast<const float2*>(qr0 + ks*16 + 8 + 2*lr);
            float2 x3 = *reinterpret_cast<const float2*>(qr1 + ks*16 + 8 + 2*lr);
            qa[ks][0] = h2u(x0.x, x0.y);
            qa[ks][1] = h2u(x1.x, x1.y);
            qa[ks][2] = h2u(x2.x, x2.y);
            qa[ks][3] = h2u(x3.x, x3.y);
        }
    }

    float accp[8][4], accr[8][4];
#pragma unroll
    for (int nt = 0; nt < 8; nt++)
#pragma unroll
        for (int i = 0; i < 4; i++) { accp[nt][i] = 0.f; accr[nt][i] = 0.f; }

    float m0 = -INFINITY, m1 = -INFINITY, s0 = 0.f, s1 = 0.f;

    const float inv_s = 0.044194173824159216f;   // 1/sqrt(512)
    const float MASKX = -1e20f * inv_s;
    const bool  lastq = (qt == S/BQ - 1);

    for (int j0 = 0; j0 < S; j0 += BJ) {
        bool doP = (j0 >= q0) || lastq;
        bool doR = (j0 <= q0);

        __syncthreads();    // all warps done with Ksm/Vt/Esm of prev tile

        // ---- stage V^T (always), K (doP), E window (doR) as fp16 ----
        for (int t = tid; t < 64*16; t += 128) {
            int r = t >> 4, e4 = (t & 15) * 4;
            float4 x = *reinterpret_cast<const float4*>(Vp + (size_t)(j0 + r)*D + e4);
            Vt[(e4+0)*VP2 + r] = __float2half(x.x);
            Vt[(e4+1)*VP2 + r] = __float2half(x.y);
            Vt[(e4+2)*VP2 + r] = __float2half(x.z);
            Vt[(e4+3)*VP2 + r] = __float2half(x.w);
        }
        if (doP) {
            for (int t = tid; t < 64*16; t += 128) {
                int r = t >> 4, e4 = (t & 15) * 4;
                float4 x = *reinterpret_cast<const float4*>(Kp + (size_t)(j0 + r)*D + e4);
                uint32_t* dst = reinterpret_cast<uint32_t*>(Ksm + r*KP2 + e4);
                dst[0] = h2u(x.x, x.y);
                dst[1] = h2u(x.z, x.w);
            }
        }
        if (doR) {
            int l0 = S - 64 - (q0 - j0);   // >= 0
            for (int t = tid; t < 128*16; t += 128) {
                int rr = t >> 4, e4 = (t & 15) * 4;
                int l = l0 + rr;
                uint32_t* dst = reinterpret_cast<uint32_t*>(Esm + rr*EP2 + e4);
                if (l < S) {
                    float4 x = *reinterpret_cast<const float4*>(E + (size_t)l*D + e4);
                    dst[0] = h2u(x.x, x.y);
                    dst[1] = h2u(x.z, x.w);
                } else {
                    dst[0] = 0u; dst[1] = 0u;
                }
            }
        }
        __syncthreads();

        if (doP) {
            // ---- scores ----
            float sc[8][4];
#pragma unroll
            for (int nt = 0; nt < 8; nt++)
#pragma unroll
                for (int i = 0; i < 4; i++) sc[nt][i] = 0.f;
#pragma unroll
            for (int ks = 0; ks < 4; ks++) {
#pragma unroll
                for (int nt = 0; nt < 8; nt++) {
                    const uint32_t* bp = reinterpret_cast<const uint32_t*>(
                        Ksm + (nt*8 + lq)*KP2 + ks*16 + 2*lr);
                    mma16(sc[nt], qa[ks][0], qa[ks][1], qa[ks][2], qa[ks][3],
                          bp[0], bp[4]);   // +8 halves = +4 uint32
                }
            }

            // ---- mask + online softmax ----
            float tm0 = -INFINITY, tm1 = -INFINITY;
#pragma unroll
            for (int nt = 0; nt < 8; nt++) {
                int jc = j0 + nt*8 + 2*lr;
                float x0 = (jc     > ilo    ) ? sc[nt][0]*inv_s : MASKX;
                float x1 = (jc + 1 > ilo    ) ? sc[nt][1]*inv_s : MASKX;
                float x2 = (jc     > ilo + 8) ? sc[nt][2]*inv_s : MASKX;
                float x3 = (jc + 1 > ilo + 8) ? sc[nt][3]*inv_s : MASKX;
                sc[nt][0] = x0; sc[nt][1] = x1; sc[nt][2] = x2; sc[nt][3] = x3;
                tm0 = fmaxf(tm0, fmaxf(x0, x1));
                tm1 = fmaxf(tm1, fmaxf(x2, x3));
            }
            tm0 = fmaxf(tm0, __shfl_xor_sync(0xffffffffu, tm0, 1));
            tm0 = fmaxf(tm0, __shfl_xor_sync(0xffffffffu, tm0, 2));
            tm1 = fmaxf(tm1, __shfl_xor_sync(0xffffffffu, tm1, 1));
            tm1 = fmaxf(tm1, __shfl_xor_sync(0xffffffffu, tm1, 2));

            float nm0 = fmaxf(m0, tm0), nm1 = fmaxf(m1, tm1);
            float cor0 = __expf(m0 - nm0), cor1 = __expf(m1 - nm1);
            m0 = nm0; m1 = nm1;

            uint32_t ph0[8], ph1[8];
            float ps0 = 0.f, ps1 = 0.f;
#pragma unroll
            for (int nt = 0; nt < 8; nt++) {
                float p0 = __expf(sc[nt][0] - nm0);
                float p1 = __expf(sc[nt][1] - nm0);
                float p2 = __expf(sc[nt][2] - nm1);
                float p3 = __expf(sc[nt][3] - nm1);
                ps0 += p0 + p1;  ps1 += p2 + p3;
                ph0[nt] = h2u(p0, p1);
                ph1[nt] = h2u(p2, p3);
            }
            ps0 += __shfl_xor_sync(0xffffffffu, ps0, 1);
            ps0 += __shfl_xor_sync(0xffffffffu, ps0, 2);
            ps1 += __shfl_xor_sync(0xffffffffu, ps1, 1);
            ps1 += __shfl_xor_sync(0xffffffffu, ps1, 2);
            s0 = s0*cor0 + ps0;
            s1 = s1*cor1 + ps1;

            // ---- accp = accp*cor + P @ V  (P straight from registers) ----
#pragma unroll
            for (int nt = 0; nt < 8; nt++) {
                accp[nt][0] *= cor0; accp[nt][1] *= cor0;
                accp[nt][2] *= cor1; accp[nt][3] *= cor1;
            }
#pragma unroll
            for (int ksv = 0; ksv < 4; ksv++) {
                uint32_t a0 = ph0[2*ksv],   a1 = ph1[2*ksv];
                uint32_t a2 = ph0[2*ksv+1], a3 = ph1[2*ksv+1];
#pragma unroll
                for (int nt = 0; nt < 8; nt++) {
                    const uint32_t* bp = reinterpret_cast<const uint32_t*>(
                        Vt + (nt*8 + lq)*VP2 + ksv*16 + 2*lr);
                    mma16(accp[nt], a0, a1, a2, a3, bp[0], bp[4]);
                }
            }
        }

        if (doR) {
            int dq = q0 - j0;

            // ---- QE = Q @ Ewin^T (two 64-col halves) + diagonal scatter ----
#pragma unroll
            for (int half = 0; half < 2; half++) {
                float qe[8][4];
#pragma unroll
                for (int nt = 0; nt < 8; nt++)
#pragma unroll
                    for (int i = 0; i < 4; i++) qe[nt][i] = 0.f;
#pragma unroll
                for (int ks = 0; ks < 4; ks++) {
#pragma unroll
                    for (int nt = 0; nt < 8; nt++) {
                        const uint32_t* bp = reinterpret_cast<const uint32_t*>(
                            Esm + (half*64 + nt*8 + lq)*EP2 + ks*16 + 2*lr);
                        mma16(qe[nt], qa[ks][0], qa[ks][1], qa[ks][2], qa[ks][3],
                              bp[0], bp[4]);
                    }
                }
#pragma unroll
                for (int nt = 0; nt < 8; nt++) {
                    int rr = half*64 + nt*8 + 2*lr;
                    int cjA = rr - 63 + rlo;
                    int cjB = cjA + 8;
                    if (cjA >= 0 && cjA < 64)
                        Psh[rlo*PP2 + cjA] =
                            __float2half((cjA <= dq + rlo) ? qe[nt][0] : 0.f);
                    if (cjA + 1 >= 0 && cjA + 1 < 64)
                        Psh[rlo*PP2 + cjA + 1] =
                            __float2half((cjA + 1 <= dq + rlo) ? qe[nt][1] : 0.f);
                    if (cjB >= 0 && cjB < 64)
                        Psh[(rlo + 8)*PP2 + cjB] =
                            __float2half((cjB <= dq + rlo + 8) ? qe[nt][2] : 0.f);
                    if (cjB + 1 >= 0 && cjB + 1 < 64)
                        Psh[(rlo + 8)*PP2 + cjB + 1] =
                            __float2half((cjB + 1 <= dq + rlo + 8) ? qe[nt][3] : 0.f);
                }
            }
            __syncwarp();

            // ---- accr += R @ V ----
#pragma unroll
            for (int ksv = 0; ksv < 4; ksv++) {
                uint32_t a0 = *reinterpret_cast<const uint32_t*>(
                    Psh +  rlo     *PP2 + ksv*16 + 2*lr);
                uint32_t a1 = *reinterpret_cast<const uint32_t*>(
                    Psh + (rlo + 8)*PP2 + ksv*16 + 2*lr);
                uint32_t a2 = *reinterpret_cast<const uint32_t*>(
                    Psh +  rlo     *PP2 + ksv*16 + 8 + 2*lr);
                uint32_t a3 = *reinterpret_cast<const uint32_t*>(
                    Psh + (rlo + 8)*PP2 + ksv*16 + 8 + 2*lr);
#pragma unroll
                for (int nt = 0; nt < 8; nt++) {
                    const uint32_t* bp = reinterpret_cast<const uint32_t*>(
                        Vt + (nt*8 + lq)*VP2 + ksv*16 + 2*lr);
                    mma16(accr[nt], a0, a1, a2, a3, bp[0], bp[4]);
                }
            }
            __syncwarp();   // done reading Psh before next tile's scatter
        }
    }

    // ---- epilogue ----
    float i0v = 1.0f / s0, i1v = 1.0f / s1;
#pragma unroll
    for (int nt = 0; nt < 8; nt++) {
        int col = h*D + nt*8 + 2*lr;
        float2 lo = make_float2(accp[nt][0]*i0v + accr[nt][0],
                                accp[nt][1]*i0v + accr[nt][1]);
        float2 hi = make_float2(accp[nt][2]*i1v + accr[nt][2],
                                accp[nt][3]*i1v + accr[nt][3]);
        *reinterpret_cast<float2*>(g_z + ((size_t)n*S + ilo    )*EMB + col) = lo;
        *reinterpret_cast<float2*>(g_z + ((size_t)n*S + ilo + 8)*EMB + col) = hi;
    }
}

// ---------------------------------------------------------------------------
// Kernel 3: out = z @ Wo.T + bo   ([4096,512] x [512,512])
// 4x4 float4 register-blocked microkernel.
// ---------------------------------------------------------------------------
__global__ __launch_bounds__(256)
void outproj_kernel(const float* __restrict__ Wo, const float* __restrict__ bo,
                    float* __restrict__ out)
{
    __shared__ float Zt[64][GP];   // Zt[e][r]
    __shared__ float Wt[64][GP];   // Wt[e][d]

    int r0  = blockIdx.x * 64;
    int d0  = blockIdx.y * 64;
    int tid = threadIdx.x;
    int tx  = tid & 15;
    int ty  = tid >> 4;

    float acc[4][4];
#pragma unroll
    for (int a = 0; a < 4; a++)
#pragma unroll
        for (int c = 0; c < 4; c++) acc[a][c] = 0.f;

    for (int e0 = 0; e0 < EMB; e0 += 64) {
        __syncthreads();
        for (int idx = tid; idx < 64*16; idx += 256) {
            int r = idx >> 4, e4 = (idx & 15) * 4;
            float4 z = *reinterpret_cast<const float4*>(g_z + (size_t)(r0 + r)*EMB + e0 + e4);
            Zt[e4+0][r] = z.x; Zt[e4+1][r] = z.y; Zt[e4+2][r] = z.z; Zt[e4+3][r] = z.w;
            float4 w = *reinterpret_cast<const float4*>(Wo + (size_t)(d0 + r)*EMB + e0 + e4);
            Wt[e4+0][r] = w.x; Wt[e4+1][r] = w.y; Wt[e4+2][r] = w.z; Wt[e4+3][r] = w.w;
        }
        __syncthreads();
#pragma unroll 8
        for (int e = 0; e < 64; e++) {
            float4 zs = *reinterpret_cast<const float4*>(&Zt[e][4*ty]);
            float4 wd = *reinterpret_cast<const float4*>(&Wt[e][4*tx]);
            float zr[4] = {zs.x, zs.y, zs.z, zs.w};
            float wr[4] = {wd.x, wd.y, wd.z, wd.w};
#pragma unroll
            for (int a = 0; a < 4; a++)
#pragma unroll
                for (int c = 0; c < 4; c++)
                    acc[a][c] += zr[a] * wr[c];
        }
    }

    float4 bb = *reinterpret_cast<const float4*>(bo + d0 + 4*tx);
#pragma unroll
    for (int a = 0; a < 4; a++) {
        float4 o = make_float4(acc[a][0] + bb.x, acc[a][1] + bb.y,
                               acc[a][2] + bb.z, acc[a][3] + bb.w);
        *reinterpret_cast<float4*>(out + (size_t)(r0 + 4*ty + a)*EMB + d0 + 4*tx) = o;
    }
}

// ---------------------------------------------------------------------------
extern "C" void kernel_launch(void* const* d_in, const int* in_sizes, int n_in,
                              void* d_out, int out_size)
{
    const float* v  = (const float*)d_in[0];
    const float* k  = (const float*)d_in[1];
    const float* q  = (const float*)d_in[2];
    const float* Wv = (const float*)d_in[3];
    const float* bv = (const float*)d_in[4];
    const float* Wk = (const float*)d_in[5];
    const float* bk = (const float*)d_in[6];
    const float* Wq = (const float*)d_in[7];
    const float* bq = (const float*)d_in[8];
    const float* E  = (const float*)d_in[9];
    const float* Wo = (const float*)d_in[10];
    const float* bo = (const float*)d_in[11];
    float* out = (float*)d_out;

    dim3 gp(NB*H*(S/64), 3);
    proj_kernel<<<gp, 256>>>(q, k, v, Wq, bq, Wk, bk, Wv, bv);

    size_t smem = (size_t)(64*KP2 + 64*VP2 + 64*PP2 + 128*EP2) * sizeof(__half);
    cudaFuncSetAttribute(attn_kernel,
                         cudaFuncAttributeMaxDynamicSharedMemorySize,
                         (int)smem);
    attn_kernel<<<NB*H*(S/BQ), 128, smem>>>(E);

    dim3 go(NB*S/64, EMB/64);
    outproj_kernel<<<go, 256>>>(Wo, bo, out);
}

// round 5
// speedup vs baseline: 8.3190x; 1.3873x over previous
#include <cuda_runtime.h>
#include <cuda_fp16.h>
#include <math.h>
#include <stdint.h>

#define S    2048
#define H    8
#define D    64
#define NB   2
#define EMB  512
#define BQ   64
#define BJ   64
#define KP   72      // halves pad (144B: ldmatrix conflict-free, 16B aligned)
#define VP   72
#define PP   72
#define EP   72
#define GP   68      // float pad for SIMT GEMM kernels

// Scratch (allocation-free rule: __device__ globals)
__device__ __half g_qh[NB*H*S*D];
__device__ __half g_kh[NB*H*S*D];
__device__ __half g_vh[NB*H*S*D];
__device__ __half g_eh[S*D];
__device__ float  g_z [NB*S*EMB];

// ---------------------------------------------------------------------------
// helpers
// ---------------------------------------------------------------------------
__device__ __forceinline__ uint32_t h2u(float a, float b) {
    __half2 h = __floats2half2_rn(a, b);
    return *reinterpret_cast<uint32_t*>(&h);
}

__device__ __forceinline__ void mma16(float c[4],
                                      uint32_t a0, uint32_t a1, uint32_t a2, uint32_t a3,
                                      uint32_t b0, uint32_t b1)
{
    asm volatile(
        "mma.sync.aligned.m16n8k16.row.col.f32.f16.f16.f32 "
        "{%0,%1,%2,%3}, {%4,%5,%6,%7}, {%8,%9}, {%0,%1,%2,%3};"
        : "+f"(c[0]), "+f"(c[1]), "+f"(c[2]), "+f"(c[3])
        : "r"(a0), "r"(a1), "r"(a2), "r"(a3), "r"(b0), "r"(b1));
}

__device__ __forceinline__ void ldsm4(uint32_t r[4], const __half* p) {
    uint32_t a = (uint32_t)__cvta_generic_to_shared(p);
    asm volatile("ldmatrix.sync.aligned.m8n8.x4.shared.b16 {%0,%1,%2,%3}, [%4];"
        : "=r"(r[0]), "=r"(r[1]), "=r"(r[2]), "=r"(r[3]) : "r"(a));
}
__device__ __forceinline__ void ldsm4t(uint32_t r[4], const __half* p) {
    uint32_t a = (uint32_t)__cvta_generic_to_shared(p);
    asm volatile("ldmatrix.sync.aligned.m8n8.x4.trans.shared.b16 {%0,%1,%2,%3}, [%4];"
        : "=r"(r[0]), "=r"(r[1]), "=r"(r[2]), "=r"(r[3]) : "r"(a));
}

// ---------------------------------------------------------------------------
// Kernel 0: convert E to fp16 once
// ---------------------------------------------------------------------------
__global__ __launch_bounds__(256)
void convE_kernel(const float* __restrict__ E)
{
    int i = blockIdx.x * blockDim.x + threadIdx.x;   // over S*D/4
    float4 x = reinterpret_cast<const float4*>(E)[i];
    uint2 u;
    u.x = h2u(x.x, x.y);
    u.y = h2u(x.z, x.w);
    reinterpret_cast<uint2*>(g_eh)[i] = u;
}

// ---------------------------------------------------------------------------
// Kernel 1: per-head projections  y = x @ W.T + b, output fp16
// ---------------------------------------------------------------------------
__global__ __launch_bounds__(256)
void proj_kernel(const float* __restrict__ q, const float* __restrict__ k,
                 const float* __restrict__ v,
                 const float* __restrict__ Wq, const float* __restrict__ bq,
                 const float* __restrict__ Wk, const float* __restrict__ bk,
                 const float* __restrict__ Wv, const float* __restrict__ bv)
{
    __shared__ float Xt[64][GP];   // Xt[e][s]
    __shared__ float Wt[64][GP];   // Wt[e][d]

    int which = blockIdx.y;
    const float* X = (which == 0) ? q  : (which == 1) ? k  : v;
    const float* W = (which == 0) ? Wq : (which == 1) ? Wk : Wv;
    const float* b = (which == 0) ? bq : (which == 1) ? bk : bv;
    __half*    Out = (which == 0) ? g_qh : (which == 1) ? g_kh : g_vh;

    int bid = blockIdx.x;
    int st  = bid % (S/64);
    int h   = (bid / (S/64)) % H;
    int n   = bid / ((S/64) * H);
    int s0  = st * 64;
    int tid = threadIdx.x;

    for (int idx = tid; idx < 64*16; idx += 256) {
        int r = idx >> 4, e4 = (idx & 15) * 4;
        float4 x = *reinterpret_cast<const float4*>(X + (size_t)(n*S + s0 + r)*EMB + h*D + e4);
        Xt[e4+0][r] = x.x; Xt[e4+1][r] = x.y; Xt[e4+2][r] = x.z; Xt[e4+3][r] = x.w;
        float4 w = *reinterpret_cast<const float4*>(W + (size_t)r*D + e4);
        Wt[e4+0][r] = w.x; Wt[e4+1][r] = w.y; Wt[e4+2][r] = w.z; Wt[e4+3][r] = w.w;
    }
    __syncthreads();

    int tx = tid & 15;
    int ty = tid >> 4;
    float acc[4][4];
#pragma unroll
    for (int a = 0; a < 4; a++)
#pragma unroll
        for (int c = 0; c < 4; c++) acc[a][c] = 0.f;

#pragma unroll 8
    for (int e = 0; e < 64; e++) {
        float4 xs = *reinterpret_cast<const float4*>(&Xt[e][4*ty]);
        float4 wd = *reinterpret_cast<const float4*>(&Wt[e][4*tx]);
        float xr[4] = {xs.x, xs.y, xs.z, xs.w};
        float wr[4] = {wd.x, wd.y, wd.z, wd.w};
#pragma unroll
        for (int a = 0; a < 4; a++)
#pragma unroll
            for (int c = 0; c < 4; c++)
                acc[a][c] += xr[a] * wr[c];
    }

    float4 bb = *reinterpret_cast<const float4*>(b + 4*tx);
#pragma unroll
    for (int a = 0; a < 4; a++) {
        uint2 o;
        o.x = h2u(acc[a][0] + bb.x, acc[a][1] + bb.y);
        o.y = h2u(acc[a][2] + bb.z, acc[a][3] + bb.w);
        *reinterpret_cast<uint2*>(Out + ((size_t)(n*H + h)*S + s0 + 4*ty + a)*D + 4*tx) = o;
    }
}

// ---------------------------------------------------------------------------
// Kernel 2: fused attention, fp16 mma + ldmatrix everywhere, fp16 staging.
// ---------------------------------------------------------------------------
__global__ __launch_bounds__(128, 3)
void attn_kernel()
{
    extern __shared__ __half smh[];
    __half* Ksm = smh;                 // [64][KP]   K[j][e]
    __half* Vsm = Ksm + 64*KP;         // [64][VP]   V[j][d] natural
    __half* Psh = Vsm + 64*VP;         // [64][PP]   R[r][j]
    __half* Esm = Psh + 64*PP;         // [128][EP]  E[l][e]

    int bid = blockIdx.x;
    int qt  = (S/BQ - 1) - (bid % (S/BQ));   // heavy tiles first
    int h   = (bid / (S/BQ)) % H;
    int n   = bid / ((S/BQ) * H);
    int q0  = qt * BQ;
    int tid  = threadIdx.x;
    int lane = tid & 31;
    int wr   = tid >> 5;
    int lq   = lane >> 2;     // 0..7
    int lr   = lane & 3;      // 0..3
    int g8   = lane >> 3;     // ldmatrix address group
    int i8   = lane & 7;

    // ldmatrix address offsets
    const int nr = (g8 >> 1)*8 + i8;    // non-trans: row within 16-block
    const int nc = (g8 & 1)*8;          // non-trans: col offset
    const int jr = (g8 & 1)*8 + i8;     // trans (V): j within 16-block
    const int dc = (g8 >> 1)*8;         // trans (V): d offset

    const __half* Qh = g_qh + (size_t)(n*H + h)*S*D;
    const __half* Kh = g_kh + (size_t)(n*H + h)*S*D;
    const __half* Vh = g_vh + (size_t)(n*H + h)*S*D;

    const int rlo = wr*16 + lq;
    const int ilo = q0 + rlo;

    // ---- Q fragments, resident for the whole block ----
    uint32_t qa[4][4];
#pragma unroll
    for (int ks = 0; ks < 4; ks++) {
        const __half* qb = Qh + (size_t)ilo*D + ks*16 + 2*lr;
        qa[ks][0] = *reinterpret_cast<const uint32_t*>(qb);
        qa[ks][1] = *reinterpret_cast<const uint32_t*>(qb + 8*D);
        qa[ks][2] = *reinterpret_cast<const uint32_t*>(qb + 8);
        qa[ks][3] = *reinterpret_cast<const uint32_t*>(qb + 8*D + 8);
    }

    float accp[8][4], accr[8][4];
#pragma unroll
    for (int nt = 0; nt < 8; nt++)
#pragma unroll
        for (int i = 0; i < 4; i++) { accp[nt][i] = 0.f; accr[nt][i] = 0.f; }

    float m0 = -INFINITY, m1 = -INFINITY, s0 = 0.f, s1 = 0.f;

    const float inv_s = 0.044194173824159216f;   // 1/sqrt(512)
    const float MASKX = -1e20f * inv_s;
    const bool  lastq = (qt == S/BQ - 1);

    for (int j0 = 0; j0 < S; j0 += BJ) {
        bool doP = (j0 >= q0) || lastq;
        bool doR = (j0 <= q0);

        __syncthreads();    // all warps done with prev tile smem

        // ---- stage tiles (pure uint4 copies; data already fp16) ----
        {
            const uint4* src = reinterpret_cast<const uint4*>(Vh + (size_t)j0*D);
#pragma unroll
            for (int t = tid; t < 512; t += 128) {
                int r = t >> 3, c = t & 7;
                *reinterpret_cast<uint4*>(Vsm + r*VP + c*8) = src[r*8 + c];
            }
        }
        if (doP) {
            const uint4* src = reinterpret_cast<const uint4*>(Kh + (size_t)j0*D);
#pragma unroll
            for (int t = tid; t < 512; t += 128) {
                int r = t >> 3, c = t & 7;
                *reinterpret_cast<uint4*>(Ksm + r*KP + c*8) = src[r*8 + c];
            }
        }
        if (doR) {
            int l0 = S - 64 - (q0 - j0);   // >= 0
#pragma unroll
            for (int t = tid; t < 1024; t += 128) {
                int r = t >> 3, c = t & 7;
                int l = l0 + r;
                uint4 z = make_uint4(0u, 0u, 0u, 0u);
                if (l < S)
                    z = *reinterpret_cast<const uint4*>(g_eh + (size_t)l*D + c*8);
                *reinterpret_cast<uint4*>(Esm + r*EP + c*8) = z;
            }
        }
        __syncthreads();

        if (doP) {
            // ---- scores ----
            float sc[8][4];
#pragma unroll
            for (int nt = 0; nt < 8; nt++)
#pragma unroll
                for (int i = 0; i < 4; i++) sc[nt][i] = 0.f;
#pragma unroll
            for (int ks = 0; ks < 4; ks++) {
#pragma unroll
                for (int nt2 = 0; nt2 < 4; nt2++) {
                    uint32_t b[4];
                    ldsm4(b, Ksm + (nt2*16 + nr)*KP + ks*16 + nc);
                    mma16(sc[2*nt2],   qa[ks][0], qa[ks][1], qa[ks][2], qa[ks][3], b[0], b[1]);
                    mma16(sc[2*nt2+1], qa[ks][0], qa[ks][1], qa[ks][2], qa[ks][3], b[2], b[3]);
                }
            }

            // ---- mask + online softmax ----
            float tm0 = -INFINITY, tm1 = -INFINITY;
#pragma unroll
            for (int nt = 0; nt < 8; nt++) {
                int jc = j0 + nt*8 + 2*lr;
                float x0 = (jc     > ilo    ) ? sc[nt][0]*inv_s : MASKX;
                float x1 = (jc + 1 > ilo    ) ? sc[nt][1]*inv_s : MASKX;
                float x2 = (jc     > ilo + 8) ? sc[nt][2]*inv_s : MASKX;
                float x3 = (jc + 1 > ilo + 8) ? sc[nt][3]*inv_s : MASKX;
                sc[nt][0] = x0; sc[nt][1] = x1; sc[nt][2] = x2; sc[nt][3] = x3;
                tm0 = fmaxf(tm0, fmaxf(x0, x1));
                tm1 = fmaxf(tm1, fmaxf(x2, x3));
            }
            tm0 = fmaxf(tm0, __shfl_xor_sync(0xffffffffu, tm0, 1));
            tm0 = fmaxf(tm0, __shfl_xor_sync(0xffffffffu, tm0, 2));
            tm1 = fmaxf(tm1, __shfl_xor_sync(0xffffffffu, tm1, 1));
            tm1 = fmaxf(tm1, __shfl_xor_sync(0xffffffffu, tm1, 2));

            float nm0 = fmaxf(m0, tm0), nm1 = fmaxf(m1, tm1);
            float cor0 = __expf(m0 - nm0), cor1 = __expf(m1 - nm1);
            m0 = nm0; m1 = nm1;

            uint32_t ph0[8], ph1[8];
            float ps0 = 0.f, ps1 = 0.f;
#pragma unroll
            for (int nt = 0; nt < 8; nt++) {
                float p0 = __expf(sc[nt][0] - nm0);
                float p1 = __expf(sc[nt][1] - nm0);
                float p2 = __expf(sc[nt][2] - nm1);
                float p3 = __expf(sc[nt][3] - nm1);
                ps0 += p0 + p1;  ps1 += p2 + p3;
                ph0[nt] = h2u(p0, p1);
                ph1[nt] = h2u(p2, p3);
            }
            ps0 += __shfl_xor_sync(0xffffffffu, ps0, 1);
            ps0 += __shfl_xor_sync(0xffffffffu, ps0, 2);
            ps1 += __shfl_xor_sync(0xffffffffu, ps1, 1);
            ps1 += __shfl_xor_sync(0xffffffffu, ps1, 2);
            s0 = s0*cor0 + ps0;
            s1 = s1*cor1 + ps1;

            // ---- accp = accp*cor + P @ V (P from registers, V via ldmatrix.trans) ----
#pragma unroll
            for (int nt = 0; nt < 8; nt++) {
                accp[nt][0] *= cor0; accp[nt][1] *= cor0;
                accp[nt][2] *= cor1; accp[nt][3] *= cor1;
            }
#pragma unroll
            for (int ksv = 0; ksv < 4; ksv++) {
                uint32_t a0 = ph0[2*ksv],   a1 = ph1[2*ksv];
                uint32_t a2 = ph0[2*ksv+1], a3 = ph1[2*ksv+1];
#pragma unroll
                for (int nt2 = 0; nt2 < 4; nt2++) {
                    uint32_t b[4];
                    ldsm4t(b, Vsm + (ksv*16 + jr)*VP + nt2*16 + dc);
                    mma16(accp[2*nt2],   a0, a1, a2, a3, b[0], b[1]);
                    mma16(accp[2*nt2+1], a0, a1, a2, a3, b[2], b[3]);
                }
            }
        }

        if (doR) {
            int dq = q0 - j0;

            // ---- QE = Q @ Ewin^T (two 64-col halves) + diagonal scatter ----
#pragma unroll
            for (int half = 0; half < 2; half++) {
                float qe[8][4];
#pragma unroll
                for (int nt = 0; nt < 8; nt++)
#pragma unroll
                    for (int i = 0; i < 4; i++) qe[nt][i] = 0.f;
#pragma unroll
                for (int ks = 0; ks < 4; ks++) {
#pragma unroll
                    for (int nt2 = 0; nt2 < 4; nt2++) {
                        uint32_t b[4];
                        ldsm4(b, Esm + (half*64 + nt2*16 + nr)*EP + ks*16 + nc);
                        mma16(qe[2*nt2],   qa[ks][0], qa[ks][1], qa[ks][2], qa[ks][3], b[0], b[1]);
                        mma16(qe[2*nt2+1], qa[ks][0], qa[ks][1], qa[ks][2], qa[ks][3], b[2], b[3]);
                    }
                }
#pragma unroll
                for (int nt = 0; nt < 8; nt++) {
                    int rr = half*64 + nt*8 + 2*lr;
                    int cjA = rr - 63 + rlo;
                    int cjB = cjA + 8;
                    if (cjA >= 0 && cjA < 64)
                        Psh[rlo*PP + cjA] =
                            __float2half((cjA <= dq + rlo) ? qe[nt][0] : 0.f);
                    if (cjA + 1 >= 0 && cjA + 1 < 64)
                        Psh[rlo*PP + cjA + 1] =
                            __float2half((cjA + 1 <= dq + rlo) ? qe[nt][1] : 0.f);
                    if (cjB >= 0 && cjB < 64)
                        Psh[(rlo + 8)*PP + cjB] =
                            __float2half((cjB <= dq + rlo + 8) ? qe[nt][2] : 0.f);
                    if (cjB + 1 >= 0 && cjB + 1 < 64)
                        Psh[(rlo + 8)*PP + cjB + 1] =
                            __float2half((cjB + 1 <= dq + rlo + 8) ? qe[nt][3] : 0.f);
                }
            }
            __syncwarp();

            // ---- accr += R @ V (A via ldmatrix from Psh, B via trans from V) ----
            const int ar = (g8 & 1)*8 + i8;     // A row within warp's 16
            const int ac = (g8 >> 1)*8;         // A col offset
#pragma unroll
            for (int ksv = 0; ksv < 4; ksv++) {
                uint32_t av[4];
                ldsm4(av, Psh + (wr*16 + ar)*PP + ksv*16 + ac);
#pragma unroll
                for (int nt2 = 0; nt2 < 4; nt2++) {
                    uint32_t b[4];
                    ldsm4t(b, Vsm + (ksv*16 + jr)*VP + nt2*16 + dc);
                    mma16(accr[2*nt2],   av[0], av[1], av[2], av[3], b[0], b[1]);
                    mma16(accr[2*nt2+1], av[0], av[1], av[2], av[3], b[2], b[3]);
                }
            }
            __syncwarp();   // done reading Psh before next tile's scatter
        }
    }

    // ---- epilogue ----
    float i0v = 1.0f / s0, i1v = 1.0f / s1;
#pragma unroll
    for (int nt = 0; nt < 8; nt++) {
        int col = h*D + nt*8 + 2*lr;
        float2 lo = make_float2(accp[nt][0]*i0v + accr[nt][0],
                                accp[nt][1]*i0v + accr[nt][1]);
        float2 hi = make_float2(accp[nt][2]*i1v + accr[nt][2],
                                accp[nt][3]*i1v + accr[nt][3]);
        *reinterpret_cast<float2*>(g_z + ((size_t)n*S + ilo    )*EMB + col) = lo;
        *reinterpret_cast<float2*>(g_z + ((size_t)n*S + ilo + 8)*EMB + col) = hi;
    }
}

// ---------------------------------------------------------------------------
// Kernel 3: out = z @ Wo.T + bo   ([4096,512] x [512,512]) fp32 SIMT
// ---------------------------------------------------------------------------
__global__ __launch_bounds__(256)
void outproj_kernel(const float* __restrict__ Wo, const float* __restrict__ bo,
                    float* __restrict__ out)
{
    __shared__ float Zt[64][GP];   // Zt[e][r]
    __shared__ float Wt[64][GP];   // Wt[e][d]

    int r0  = blockIdx.x * 64;
    int d0  = blockIdx.y * 64;
    int tid = threadIdx.x;
    int tx  = tid & 15;
    int ty  = tid >> 4;

    float acc[4][4];
#pragma unroll
    for (int a = 0; a < 4; a++)
#pragma unroll
        for (int c = 0; c < 4; c++) acc[a][c] = 0.f;

    for (int e0 = 0; e0 < EMB; e0 += 64) {
        __syncthreads();
        for (int idx = tid; idx < 64*16; idx += 256) {
            int r = idx >> 4, e4 = (idx & 15) * 4;
            float4 z = *reinterpret_cast<const float4*>(g_z + (size_t)(r0 + r)*EMB + e0 + e4);
            Zt[e4+0][r] = z.x; Zt[e4+1][r] = z.y; Zt[e4+2][r] = z.z; Zt[e4+3][r] = z.w;
            float4 w = *reinterpret_cast<const float4*>(Wo + (size_t)(d0 + r)*EMB + e0 + e4);
            Wt[e4+0][r] = w.x; Wt[e4+1][r] = w.y; Wt[e4+2][r] = w.z; Wt[e4+3][r] = w.w;
        }
        __syncthreads();
#pragma unroll 8
        for (int e = 0; e < 64; e++) {
            float4 zs = *reinterpret_cast<const float4*>(&Zt[e][4*ty]);
            float4 wd = *reinterpret_cast<const float4*>(&Wt[e][4*tx]);
            float zr[4] = {zs.x, zs.y, zs.z, zs.w};
            float wr[4] = {wd.x, wd.y, wd.z, wd.w};
#pragma unroll
            for (int a = 0; a < 4; a++)
#pragma unroll
                for (int c = 0; c < 4; c++)
                    acc[a][c] += zr[a] * wr[c];
        }
    }

    float4 bb = *reinterpret_cast<const float4*>(bo + d0 + 4*tx);
#pragma unroll
    for (int a = 0; a < 4; a++) {
        float4 o = make_float4(acc[a][0] + bb.x, acc[a][1] + bb.y,
                               acc[a][2] + bb.z, acc[a][3] + bb.w);
        *reinterpret_cast<float4*>(out + (size_t)(r0 + 4*ty + a)*EMB + d0 + 4*tx) = o;
    }
}

// ---------------------------------------------------------------------------
extern "C" void kernel_launch(void* const* d_in, const int* in_sizes, int n_in,
                              void* d_out, int out_size)
{
    const float* v  = (const float*)d_in[0];
    const float* k  = (const float*)d_in[1];
    const float* q  = (const float*)d_in[2];
    const float* Wv = (const float*)d_in[3];
    const float* bv = (const float*)d_in[4];
    const float* Wk = (const float*)d_in[5];
    const float* bk = (const float*)d_in[6];
    const float* Wq = (const float*)d_in[7];
    const float* bq = (const float*)d_in[8];
    const float* E  = (const float*)d_in[9];
    const float* Wo = (const float*)d_in[10];
    const float* bo = (const float*)d_in[11];
    float* out = (float*)d_out;

    convE_kernel<<<S*D/4/256, 256>>>(E);

    dim3 gp(NB*H*(S/64), 3);
    proj_kernel<<<gp, 256>>>(q, k, v, Wq, bq, Wk, bk, Wv, bv);

    size_t smem = (size_t)(64*KP + 64*VP + 64*PP + 128*EP) * sizeof(__half);
    cudaFuncSetAttribute(attn_kernel,
                         cudaFuncAttributeMaxDynamicSharedMemorySize,
                         (int)smem);
    attn_kernel<<<NB*H*(S/BQ), 128, smem>>>();

    dim3 go(NB*S/64, EMB/64);
    outproj_kernel<<<go, 256>>>(Wo, bo, out);
}

// round 6
// speedup vs baseline: 11.3969x; 1.3700x over previous
#include <cuda_runtime.h>
#include <cuda_fp16.h>
#include <math.h>
#include <stdint.h>

#define S    2048
#define H    8
#define D    64
#define NB   2
#define EMB  512
#define BQ   64
#define BJ   64
#define KP   72      // halves pad (144B: ldmatrix conflict-free, 16B aligned)
#define VP   72
#define PP   72
#define EP   72
#define ZP   72
#define GP   68      // float pad for SIMT GEMM kernels

// Scratch (allocation-free rule: __device__ globals)
__device__ __half g_qh[NB*H*S*D];
__device__ __half g_kh[NB*H*S*D];
__device__ __half g_vh[NB*H*S*D];
__device__ __half g_eh[S*D];
__device__ __half g_wo[EMB*EMB];
__device__ __half g_z [NB*S*EMB];

// ---------------------------------------------------------------------------
// helpers
// ---------------------------------------------------------------------------
__device__ __forceinline__ uint32_t h2u(float a, float b) {
    __half2 h = __floats2half2_rn(a, b);
    return *reinterpret_cast<uint32_t*>(&h);
}

__device__ __forceinline__ void mma16(float c[4],
                                      uint32_t a0, uint32_t a1, uint32_t a2, uint32_t a3,
                                      uint32_t b0, uint32_t b1)
{
    asm volatile(
        "mma.sync.aligned.m16n8k16.row.col.f32.f16.f16.f32 "
        "{%0,%1,%2,%3}, {%4,%5,%6,%7}, {%8,%9}, {%0,%1,%2,%3};"
        : "+f"(c[0]), "+f"(c[1]), "+f"(c[2]), "+f"(c[3])
        : "r"(a0), "r"(a1), "r"(a2), "r"(a3), "r"(b0), "r"(b1));
}

__device__ __forceinline__ void ldsm4(uint32_t r[4], const __half* p) {
    uint32_t a = (uint32_t)__cvta_generic_to_shared(p);
    asm volatile("ldmatrix.sync.aligned.m8n8.x4.shared.b16 {%0,%1,%2,%3}, [%4];"
        : "=r"(r[0]), "=r"(r[1]), "=r"(r[2]), "=r"(r[3]) : "r"(a));
}
__device__ __forceinline__ void ldsm4t(uint32_t r[4], const __half* p) {
    uint32_t a = (uint32_t)__cvta_generic_to_shared(p);
    asm volatile("ldmatrix.sync.aligned.m8n8.x4.trans.shared.b16 {%0,%1,%2,%3}, [%4];"
        : "=r"(r[0]), "=r"(r[1]), "=r"(r[2]), "=r"(r[3]) : "r"(a));
}

// ---------------------------------------------------------------------------
// Kernel 0a: convert E to fp16 once
// ---------------------------------------------------------------------------
__global__ __launch_bounds__(256)
void convE_kernel(const float* __restrict__ E)
{
    int i = blockIdx.x * blockDim.x + threadIdx.x;   // over S*D/4
    float4 x = reinterpret_cast<const float4*>(E)[i];
    uint2 u;
    u.x = h2u(x.x, x.y);
    u.y = h2u(x.z, x.w);
    reinterpret_cast<uint2*>(g_eh)[i] = u;
}

// ---------------------------------------------------------------------------
// Kernel 0b: convert Wo to fp16 once
// ---------------------------------------------------------------------------
__global__ __launch_bounds__(256)
void convW_kernel(const float* __restrict__ Wo)
{
    int i = blockIdx.x * blockDim.x + threadIdx.x;   // over EMB*EMB/4
    float4 x = reinterpret_cast<const float4*>(Wo)[i];
    uint2 u;
    u.x = h2u(x.x, x.y);
    u.y = h2u(x.z, x.w);
    reinterpret_cast<uint2*>(g_wo)[i] = u;
}

// ---------------------------------------------------------------------------
// Kernel 1: per-head projections  y = x @ W.T + b, output fp16 (fp32 math)
// ---------------------------------------------------------------------------
__global__ __launch_bounds__(256)
void proj_kernel(const float* __restrict__ q, const float* __restrict__ k,
                 const float* __restrict__ v,
                 const float* __restrict__ Wq, const float* __restrict__ bq,
                 const float* __restrict__ Wk, const float* __restrict__ bk,
                 const float* __restrict__ Wv, const float* __restrict__ bv)
{
    __shared__ float Xt[64][GP];   // Xt[e][s]
    __shared__ float Wt[64][GP];   // Wt[e][d]

    int which = blockIdx.y;
    const float* X = (which == 0) ? q  : (which == 1) ? k  : v;
    const float* W = (which == 0) ? Wq : (which == 1) ? Wk : Wv;
    const float* b = (which == 0) ? bq : (which == 1) ? bk : bv;
    __half*    Out = (which == 0) ? g_qh : (which == 1) ? g_kh : g_vh;

    int bid = blockIdx.x;
    int st  = bid % (S/64);
    int h   = (bid / (S/64)) % H;
    int n   = bid / ((S/64) * H);
    int s0  = st * 64;
    int tid = threadIdx.x;

    for (int idx = tid; idx < 64*16; idx += 256) {
        int r = idx >> 4, e4 = (idx & 15) * 4;
        float4 x = *reinterpret_cast<const float4*>(X + (size_t)(n*S + s0 + r)*EMB + h*D + e4);
        Xt[e4+0][r] = x.x; Xt[e4+1][r] = x.y; Xt[e4+2][r] = x.z; Xt[e4+3][r] = x.w;
        float4 w = *reinterpret_cast<const float4*>(W + (size_t)r*D + e4);
        Wt[e4+0][r] = w.x; Wt[e4+1][r] = w.y; Wt[e4+2][r] = w.z; Wt[e4+3][r] = w.w;
    }
    __syncthreads();

    int tx = tid & 15;
    int ty = tid >> 4;
    float acc[4][4];
#pragma unroll
    for (int a = 0; a < 4; a++)
#pragma unroll
        for (int c = 0; c < 4; c++) acc[a][c] = 0.f;

#pragma unroll 8
    for (int e = 0; e < 64; e++) {
        float4 xs = *reinterpret_cast<const float4*>(&Xt[e][4*ty]);
        float4 wd = *reinterpret_cast<const float4*>(&Wt[e][4*tx]);
        float xr[4] = {xs.x, xs.y, xs.z, xs.w};
        float wr[4] = {wd.x, wd.y, wd.z, wd.w};
#pragma unroll
        for (int a = 0; a < 4; a++)
#pragma unroll
            for (int c = 0; c < 4; c++)
                acc[a][c] += xr[a] * wr[c];
    }

    float4 bb = *reinterpret_cast<const float4*>(b + 4*tx);
#pragma unroll
    for (int a = 0; a < 4; a++) {
        uint2 o;
        o.x = h2u(acc[a][0] + bb.x, acc[a][1] + bb.y);
        o.y = h2u(acc[a][2] + bb.z, acc[a][3] + bb.w);
        *reinterpret_cast<uint2*>(Out + ((size_t)(n*H + h)*S + s0 + 4*ty + a)*D + 4*tx) = o;
    }
}

// ---------------------------------------------------------------------------
// Kernel 2: fused attention, fp16 mma + ldmatrix everywhere, fp16 staging.
// Writes z as fp16.
// ---------------------------------------------------------------------------
__global__ __launch_bounds__(128, 3)
void attn_kernel()
{
    extern __shared__ __half smh[];
    __half* Ksm = smh;                 // [64][KP]   K[j][e]
    __half* Vsm = Ksm + 64*KP;         // [64][VP]   V[j][d] natural
    __half* Psh = Vsm + 64*VP;         // [64][PP]   R[r][j]
    __half* Esm = Psh + 64*PP;         // [128][EP]  E[l][e]

    int bid = blockIdx.x;
    int qt  = (S/BQ - 1) - (bid % (S/BQ));   // heavy tiles first
    int h   = (bid / (S/BQ)) % H;
    int n   = bid / ((S/BQ) * H);
    int q0  = qt * BQ;
    int tid  = threadIdx.x;
    int lane = tid & 31;
    int wr   = tid >> 5;
    int lq   = lane >> 2;     // 0..7
    int lr   = lane & 3;      // 0..3
    int g8   = lane >> 3;     // ldmatrix address group
    int i8   = lane & 7;

    // ldmatrix address offsets
    const int nr = (g8 >> 1)*8 + i8;    // non-trans B: row within 16-block
    const int nc = (g8 & 1)*8;          // non-trans B: col offset
    const int jr = (g8 & 1)*8 + i8;     // trans (V): j within 16-block
    const int dc = (g8 >> 1)*8;         // trans (V): d offset

    const __half* Qh = g_qh + (size_t)(n*H + h)*S*D;
    const __half* Kh = g_kh + (size_t)(n*H + h)*S*D;
    const __half* Vh = g_vh + (size_t)(n*H + h)*S*D;

    const int rlo = wr*16 + lq;
    const int ilo = q0 + rlo;

    // ---- Q fragments, resident for the whole block ----
    uint32_t qa[4][4];
#pragma unroll
    for (int ks = 0; ks < 4; ks++) {
        const __half* qb = Qh + (size_t)ilo*D + ks*16 + 2*lr;
        qa[ks][0] = *reinterpret_cast<const uint32_t*>(qb);
        qa[ks][1] = *reinterpret_cast<const uint32_t*>(qb + 8*D);
        qa[ks][2] = *reinterpret_cast<const uint32_t*>(qb + 8);
        qa[ks][3] = *reinterpret_cast<const uint32_t*>(qb + 8*D + 8);
    }

    float accp[8][4], accr[8][4];
#pragma unroll
    for (int nt = 0; nt < 8; nt++)
#pragma unroll
        for (int i = 0; i < 4; i++) { accp[nt][i] = 0.f; accr[nt][i] = 0.f; }

    float m0 = -INFINITY, m1 = -INFINITY, s0 = 0.f, s1 = 0.f;

    const float inv_s = 0.044194173824159216f;   // 1/sqrt(512)
    const float MASKX = -1e20f * inv_s;
    const bool  lastq = (qt == S/BQ - 1);

    for (int j0 = 0; j0 < S; j0 += BJ) {
        bool doP = (j0 >= q0) || lastq;
        bool doR = (j0 <= q0);

        __syncthreads();    // all warps done with prev tile smem

        // ---- stage tiles (pure uint4 copies; data already fp16) ----
        {
            const uint4* src = reinterpret_cast<const uint4*>(Vh + (size_t)j0*D);
#pragma unroll
            for (int t = tid; t < 512; t += 128) {
                int r = t >> 3, c = t & 7;
                *reinterpret_cast<uint4*>(Vsm + r*VP + c*8) = src[r*8 + c];
            }
        }
        if (doP) {
            const uint4* src = reinterpret_cast<const uint4*>(Kh + (size_t)j0*D);
#pragma unroll
            for (int t = tid; t < 512; t += 128) {
                int r = t >> 3, c = t & 7;
                *reinterpret_cast<uint4*>(Ksm + r*KP + c*8) = src[r*8 + c];
            }
        }
        if (doR) {
            int l0 = S - 64 - (q0 - j0);   // >= 0
#pragma unroll
            for (int t = tid; t < 1024; t += 128) {
                int r = t >> 3, c = t & 7;
                int l = l0 + r;
                uint4 z = make_uint4(0u, 0u, 0u, 0u);
                if (l < S)
                    z = *reinterpret_cast<const uint4*>(g_eh + (size_t)l*D + c*8);
                *reinterpret_cast<uint4*>(Esm + r*EP + c*8) = z;
            }
        }
        __syncthreads();

        if (doP) {
            // ---- scores ----
            float sc[8][4];
#pragma unroll
            for (int nt = 0; nt < 8; nt++)
#pragma unroll
                for (int i = 0; i < 4; i++) sc[nt][i] = 0.f;
#pragma unroll
            for (int ks = 0; ks < 4; ks++) {
#pragma unroll
                for (int nt2 = 0; nt2 < 4; nt2++) {
                    uint32_t b[4];
                    ldsm4(b, Ksm + (nt2*16 + nr)*KP + ks*16 + nc);
                    mma16(sc[2*nt2],   qa[ks][0], qa[ks][1], qa[ks][2], qa[ks][3], b[0], b[1]);
                    mma16(sc[2*nt2+1], qa[ks][0], qa[ks][1], qa[ks][2], qa[ks][3], b[2], b[3]);
                }
            }

            // ---- mask + online softmax ----
            float tm0 = -INFINITY, tm1 = -INFINITY;
#pragma unroll
            for (int nt = 0; nt < 8; nt++) {
                int jc = j0 + nt*8 + 2*lr;
                float x0 = (jc     > ilo    ) ? sc[nt][0]*inv_s : MASKX;
                float x1 = (jc + 1 > ilo    ) ? sc[nt][1]*inv_s : MASKX;
                float x2 = (jc     > ilo + 8) ? sc[nt][2]*inv_s : MASKX;
                float x3 = (jc + 1 > ilo + 8) ? sc[nt][3]*inv_s : MASKX;
                sc[nt][0] = x0; sc[nt][1] = x1; sc[nt][2] = x2; sc[nt][3] = x3;
                tm0 = fmaxf(tm0, fmaxf(x0, x1));
                tm1 = fmaxf(tm1, fmaxf(x2, x3));
            }
            tm0 = fmaxf(tm0, __shfl_xor_sync(0xffffffffu, tm0, 1));
            tm0 = fmaxf(tm0, __shfl_xor_sync(0xffffffffu, tm0, 2));
            tm1 = fmaxf(tm1, __shfl_xor_sync(0xffffffffu, tm1, 1));
            tm1 = fmaxf(tm1, __shfl_xor_sync(0xffffffffu, tm1, 2));

            float nm0 = fmaxf(m0, tm0), nm1 = fmaxf(m1, tm1);
            float cor0 = __expf(m0 - nm0), cor1 = __expf(m1 - nm1);
            m0 = nm0; m1 = nm1;

            uint32_t ph0[8], ph1[8];
            float ps0 = 0.f, ps1 = 0.f;
#pragma unroll
            for (int nt = 0; nt < 8; nt++) {
                float p0 = __expf(sc[nt][0] - nm0);
                float p1 = __expf(sc[nt][1] - nm0);
                float p2 = __expf(sc[nt][2] - nm1);
                float p3 = __expf(sc[nt][3] - nm1);
                ps0 += p0 + p1;  ps1 += p2 + p3;
                ph0[nt] = h2u(p0, p1);
                ph1[nt] = h2u(p2, p3);
            }
            ps0 += __shfl_xor_sync(0xffffffffu, ps0, 1);
            ps0 += __shfl_xor_sync(0xffffffffu, ps0, 2);
            ps1 += __shfl_xor_sync(0xffffffffu, ps1, 1);
            ps1 += __shfl_xor_sync(0xffffffffu, ps1, 2);
            s0 = s0*cor0 + ps0;
            s1 = s1*cor1 + ps1;

            // ---- accp = accp*cor + P @ V (P from registers, V via ldmatrix.trans) ----
#pragma unroll
            for (int nt = 0; nt < 8; nt++) {
                accp[nt][0] *= cor0; accp[nt][1] *= cor0;
                accp[nt][2] *= cor1; accp[nt][3] *= cor1;
            }
#pragma unroll
            for (int ksv = 0; ksv < 4; ksv++) {
                uint32_t a0 = ph0[2*ksv],   a1 = ph1[2*ksv];
                uint32_t a2 = ph0[2*ksv+1], a3 = ph1[2*ksv+1];
#pragma unroll
                for (int nt2 = 0; nt2 < 4; nt2++) {
                    uint32_t b[4];
                    ldsm4t(b, Vsm + (ksv*16 + jr)*VP + nt2*16 + dc);
                    mma16(accp[2*nt2],   a0, a1, a2, a3, b[0], b[1]);
                    mma16(accp[2*nt2+1], a0, a1, a2, a3, b[2], b[3]);
                }
            }
        }

        if (doR) {
            int dq = q0 - j0;

            // ---- QE = Q @ Ewin^T (two 64-col halves) + diagonal scatter ----
#pragma unroll
            for (int half = 0; half < 2; half++) {
                float qe[8][4];
#pragma unroll
                for (int nt = 0; nt < 8; nt++)
#pragma unroll
                    for (int i = 0; i < 4; i++) qe[nt][i] = 0.f;
#pragma unroll
                for (int ks = 0; ks < 4; ks++) {
#pragma unroll
                    for (int nt2 = 0; nt2 < 4; nt2++) {
                        uint32_t b[4];
                        ldsm4(b, Esm + (half*64 + nt2*16 + nr)*EP + ks*16 + nc);
                        mma16(qe[2*nt2],   qa[ks][0], qa[ks][1], qa[ks][2], qa[ks][3], b[0], b[1]);
                        mma16(qe[2*nt2+1], qa[ks][0], qa[ks][1], qa[ks][2], qa[ks][3], b[2], b[3]);
                    }
                }
#pragma unroll
                for (int nt = 0; nt < 8; nt++) {
                    int rr = half*64 + nt*8 + 2*lr;
                    int cjA = rr - 63 + rlo;
                    int cjB = cjA + 8;
                    if (cjA >= 0 && cjA < 64)
                        Psh[rlo*PP + cjA] =
                            __float2half((cjA <= dq + rlo) ? qe[nt][0] : 0.f);
                    if (cjA + 1 >= 0 && cjA + 1 < 64)
                        Psh[rlo*PP + cjA + 1] =
                            __float2half((cjA + 1 <= dq + rlo) ? qe[nt][1] : 0.f);
                    if (cjB >= 0 && cjB < 64)
                        Psh[(rlo + 8)*PP + cjB] =
                            __float2half((cjB <= dq + rlo + 8) ? qe[nt][2] : 0.f);
                    if (cjB + 1 >= 0 && cjB + 1 < 64)
                        Psh[(rlo + 8)*PP + cjB + 1] =
                            __float2half((cjB + 1 <= dq + rlo + 8) ? qe[nt][3] : 0.f);
                }
            }
            __syncwarp();

            // ---- accr += R @ V (A via ldmatrix from Psh, B via trans from V) ----
            const int ar = (g8 & 1)*8 + i8;     // A row within warp's 16
            const int ac = (g8 >> 1)*8;         // A col offset
#pragma unroll
            for (int ksv = 0; ksv < 4; ksv++) {
                uint32_t av[4];
                ldsm4(av, Psh + (wr*16 + ar)*PP + ksv*16 + ac);
#pragma unroll
                for (int nt2 = 0; nt2 < 4; nt2++) {
                    uint32_t b[4];
                    ldsm4t(b, Vsm + (ksv*16 + jr)*VP + nt2*16 + dc);
                    mma16(accr[2*nt2],   av[0], av[1], av[2], av[3], b[0], b[1]);
                    mma16(accr[2*nt2+1], av[0], av[1], av[2], av[3], b[2], b[3]);
                }
            }
            __syncwarp();   // done reading Psh before next tile's scatter
        }
    }

    // ---- epilogue (fp16 z) ----
    float i0v = 1.0f / s0, i1v = 1.0f / s1;
#pragma unroll
    for (int nt = 0; nt < 8; nt++) {
        int col = h*D + nt*8 + 2*lr;
        uint32_t lo = h2u(accp[nt][0]*i0v + accr[nt][0],
                          accp[nt][1]*i0v + accr[nt][1]);
        uint32_t hi = h2u(accp[nt][2]*i1v + accr[nt][2],
                          accp[nt][3]*i1v + accr[nt][3]);
        *reinterpret_cast<uint32_t*>(g_z + ((size_t)n*S + ilo    )*EMB + col) = lo;
        *reinterpret_cast<uint32_t*>(g_z + ((size_t)n*S + ilo + 8)*EMB + col) = hi;
    }
}

// ---------------------------------------------------------------------------
// Kernel 3: out = z @ Wo.T + bo  on fp16 tensor cores, fp32 accum + bias.
// 128 threads / 4 warps; warp owns 16 rows x 64 cols of a 64x64 tile.
// ---------------------------------------------------------------------------
__global__ __launch_bounds__(128)
void outproj_kernel(const float* __restrict__ bo, float* __restrict__ out)
{
    __shared__ __half Zs[64*ZP];   // z  tile [row][e]
    __shared__ __half Ws[64*ZP];   // Wo tile [dout][e]

    int r0  = blockIdx.x * 64;
    int d0  = blockIdx.y * 64;
    int tid  = threadIdx.x;
    int lane = tid & 31;
    int wr   = tid >> 5;
    int lq   = lane >> 2;
    int lr   = lane & 3;
    int g8   = lane >> 3;
    int i8   = lane & 7;

    const int ar = (g8 & 1)*8 + i8;     // A (z) ldmatrix row
    const int ac = (g8 >> 1)*8;         // A col offset
    const int nr = (g8 >> 1)*8 + i8;    // B (Wo) ldmatrix row
    const int nc = (g8 & 1)*8;          // B col offset

    float acc[8][4];
#pragma unroll
    for (int nt = 0; nt < 8; nt++)
#pragma unroll
        for (int i = 0; i < 4; i++) acc[nt][i] = 0.f;

    for (int e0 = 0; e0 < EMB; e0 += 64) {
        __syncthreads();
#pragma unroll
        for (int t = tid; t < 512; t += 128) {
            int r = t >> 3, c = t & 7;
            *reinterpret_cast<uint4*>(Zs + r*ZP + c*8) =
                *reinterpret_cast<const uint4*>(g_z + (size_t)(r0 + r)*EMB + e0 + c*8);
            *reinterpret_cast<uint4*>(Ws + r*ZP + c*8) =
                *reinterpret_cast<const uint4*>(g_wo + (size_t)(d0 + r)*EMB + e0 + c*8);
        }
        __syncthreads();

#pragma unroll
        for (int ks = 0; ks < 4; ks++) {
            uint32_t av[4];
            ldsm4(av, Zs + (wr*16 + ar)*ZP + ks*16 + ac);
#pragma unroll
            for (int nt2 = 0; nt2 < 4; nt2++) {
                uint32_t b[4];
                ldsm4(b, Ws + (nt2*16 + nr)*ZP + ks*16 + nc);
                mma16(acc[2*nt2],   av[0], av[1], av[2], av[3], b[0], b[1]);
                mma16(acc[2*nt2+1], av[0], av[1], av[2], av[3], b[2], b[3]);
            }
        }
    }

    int row = r0 + wr*16 + lq;
#pragma unroll
    for (int nt = 0; nt < 8; nt++) {
        int col = d0 + nt*8 + 2*lr;
        float2 bb = *reinterpret_cast<const float2*>(bo + col);
        float2 lo = make_float2(acc[nt][0] + bb.x, acc[nt][1] + bb.y);
        float2 hi = make_float2(acc[nt][2] + bb.x, acc[nt][3] + bb.y);
        *reinterpret_cast<float2*>(out + (size_t)row*EMB + col) = lo;
        *reinterpret_cast<float2*>(out + (size_t)(row + 8)*EMB + col) = hi;
    }
}

// ---------------------------------------------------------------------------
extern "C" void kernel_launch(void* const* d_in, const int* in_sizes, int n_in,
                              void* d_out, int out_size)
{
    const float* v  = (const float*)d_in[0];
    const float* k  = (const float*)d_in[1];
    const float* q  = (const float*)d_in[2];
    const float* Wv = (const float*)d_in[3];
    const float* bv = (const float*)d_in[4];
    const float* Wk = (const float*)d_in[5];
    const float* bk = (const float*)d_in[6];
    const float* Wq = (const float*)d_in[7];
    const float* bq = (const float*)d_in[8];
    const float* E  = (const float*)d_in[9];
    const float* Wo = (const float*)d_in[10];
    const float* bo = (const float*)d_in[11];
    float* out = (float*)d_out;

    convE_kernel<<<S*D/4/256, 256>>>(E);
    convW_kernel<<<EMB*EMB/4/256, 256>>>(Wo);

    dim3 gp(NB*H*(S/64), 3);
    proj_kernel<<<gp, 256>>>(q, k, v, Wq, bq, Wk, bk, Wv, bv);

    size_t smem = (size_t)(64*KP + 64*VP + 64*PP + 128*EP) * sizeof(__half);
    cudaFuncSetAttribute(attn_kernel,
                         cudaFuncAttributeMaxDynamicSharedMemorySize,
                         (int)smem);
    attn_kernel<<<NB*H*(S/BQ), 128, smem>>>();

    dim3 go(NB*S/64, EMB/64);
    outproj_kernel<<<go, 128>>>(bo, out);
}